// round 13
// baseline (speedup 1.0000x reference)
#include <cuda_runtime.h>
#include <cuda_bf16.h>
#include <cstdint>

#define BSZ    1024
#define TSTEPS 128
#define INDIM  256
#define HID    64
#define FREQ   10
#define OUTD   16
#define NW     266     // packed gate cols: i(64) | ste(64) | fre(10) | c(64) | o(64)
#define NPAD   288     // padded N: 3 tiles of 96
#define MROWS  (BSZ * TSTEPS)
#define NB     2       // batch elements per recurrent block

typedef unsigned long long u64;

// ----------------- device globals (no runtime allocation) -----------------
__device__ __align__(16) float d_pre[(size_t)MROWS * NW];      // (t*1024+b, 266) fp32
__device__ __align__(16) __nv_bfloat16 d_Bhi[NPAD * INDIM];    // [n][k] bf16 hi
__device__ __align__(16) __nv_bfloat16 d_Blo[NPAD * INDIM];    // [n][k] bf16 lo
__device__ __align__(8)  float d_bpack[NPAD];
__device__ float d_Upk[4 * HID * HID];                          // interleaved [m][k4][j][kk]
__device__ float d_Ufpk[16 * FREQ * 4];
__device__ float d_cosT[TSTEPS * FREQ];
__device__ float d_sinT[TSTEPS * FREQ];

__device__ __forceinline__ float hsig(float x) {
    return fminf(fmaxf(x * (1.0f / 6.0f) + 0.5f, 0.0f), 1.0f);
}
__device__ __forceinline__ float tanh_fast(float x) {
    float y; asm("tanh.approx.f32 %0, %1;" : "=f"(y) : "f"(x)); return y;
}

// ---- packed f32x2 helpers (state update only) ----
__device__ __forceinline__ u64 pack2f(float lo, float hi) {
    u64 r; asm("mov.b64 %0, {%1, %2};" : "=l"(r) : "f"(lo), "f"(hi)); return r;
}
__device__ __forceinline__ float2 unpack2f(u64 v) {
    float2 r; asm("mov.b64 {%0, %1}, %2;" : "=f"(r.x), "=f"(r.y) : "l"(v)); return r;
}
__device__ __forceinline__ u64 dup2f(float x) { return pack2f(x, x); }
__device__ __forceinline__ u64 fma2(u64 a, u64 b, u64 c) {
    u64 d; asm("fma.rn.f32x2 %0, %1, %2, %3;" : "=l"(d) : "l"(a), "l"(b), "l"(c)); return d;
}
__device__ __forceinline__ u64 mul2(u64 a, u64 b) {
    u64 d; asm("mul.rn.f32x2 %0, %1, %2;" : "=l"(d) : "l"(a), "l"(b)); return d;
}
__device__ __forceinline__ u64 add2(u64 a, u64 b) {
    u64 d; asm("add.rn.f32x2 %0, %1, %2;" : "=l"(d) : "l"(a), "l"(b)); return d;
}

__device__ __forceinline__ uint32_t smem_u32(const void* p) {
    uint32_t a;
    asm("{ .reg .u64 t; cvta.to.shared.u64 t, %1; cvt.u32.u64 %0, t; }" : "=r"(a) : "l"(p));
    return a;
}

// ---- base-ISA async copy / mma helpers (no sm_103a-only features) ----
__device__ __forceinline__ void cp16(uint32_t dst, const void* src) {
    asm volatile("cp.async.cg.shared.global [%0], [%1], 16;" :: "r"(dst), "l"(src));
}
#define CP_COMMIT()  asm volatile("cp.async.commit_group;" ::: "memory")
#define CP_WAIT(N)   asm volatile("cp.async.wait_group %0;" :: "n"(N) : "memory")

#define LDSM4(r0, r1, r2, r3, addr) \
    asm volatile("ldmatrix.sync.aligned.m8n8.x4.shared.b16 {%0,%1,%2,%3}, [%4];" \
        : "=r"(r0), "=r"(r1), "=r"(r2), "=r"(r3) : "r"(addr))

#define MMA16816(d, a, b0, b1) \
    asm volatile("mma.sync.aligned.m16n8k16.row.col.f32.bf16.bf16.f32 " \
        "{%0,%1,%2,%3}, {%4,%5,%6,%7}, {%8,%9}, {%0,%1,%2,%3};" \
        : "+f"((d)[0]), "+f"((d)[1]), "+f"((d)[2]), "+f"((d)[3]) \
        : "r"((a)[0]), "r"((a)[1]), "r"((a)[2]), "r"((a)[3]), "r"(b0), "r"(b1))

// ---------------- pack W_* -> Bhi/Blo [288][256] bf16 (+ biases fp32) ---------------
__global__ void pack_w_kernel(const float* __restrict__ W_i,  const float* __restrict__ b_i,
                              const float* __restrict__ W_ste,const float* __restrict__ b_ste,
                              const float* __restrict__ W_fre,const float* __restrict__ b_fre,
                              const float* __restrict__ W_c,  const float* __restrict__ b_c,
                              const float* __restrict__ W_o,  const float* __restrict__ b_o)
{
    int n = blockIdx.x;      // 0..287
    int k = threadIdx.x;     // 0..255
    float w = 0.f, bias = 0.f;
    if (n < 64)       { w = W_i  [k * HID  + n];         bias = b_i  [n]; }
    else if (n < 128) { w = W_ste[k * HID  + (n - 64)];  bias = b_ste[n - 64]; }
    else if (n < 138) { w = W_fre[k * FREQ + (n - 128)]; bias = b_fre[n - 128]; }
    else if (n < 202) { w = W_c  [k * HID  + (n - 138)]; bias = b_c  [n - 138]; }
    else if (n < 266) { w = W_o  [k * HID  + (n - 202)]; bias = b_o  [n - 202]; }
    __nv_bfloat16 h = __float2bfloat16(w);
    __nv_bfloat16 l = __float2bfloat16(w - __bfloat162float(h));
    d_Bhi[n * INDIM + k] = h;
    d_Blo[n * INDIM + k] = l;
    if (k == 0) d_bpack[n] = bias;
}

// -------- interleave U so thread j's float4 = U[4*k4 .. 4*k4+3][j] (warp = 512B) ----
__global__ void pack_u_kernel(const float* __restrict__ U_i, const float* __restrict__ U_ste,
                              const float* __restrict__ U_c, const float* __restrict__ U_o,
                              const float* __restrict__ U_fre)
{
    int idx = blockIdx.x * blockDim.x + threadIdx.x;   // 16 x 256 = 4096
    int k4 = idx >> 8, j = (idx >> 2) & 63, kk = idx & 3;
    int k = 4 * k4 + kk;
    d_Upk[0 * 4096 + idx] = U_i  [k * HID + j];
    d_Upk[1 * 4096 + idx] = U_ste[k * HID + j];
    d_Upk[2 * 4096 + idx] = U_c  [k * HID + j];
    d_Upk[3 * 4096 + idx] = U_o  [k * HID + j];
    if (idx < 16 * FREQ * 4) {
        int fk4 = idx / (FREQ * 4), rr = idx % (FREQ * 4);
        int fj = rr >> 2, fkk = rr & 3;
        d_Ufpk[idx] = U_fre[(4 * fk4 + fkk) * FREQ + fj];
    }
}

// ---------------- trig table, replicating reference fp32 arithmetic ------------------
__global__ void trig_kernel()
{
    int idx = blockIdx.x * blockDim.x + threadIdx.x;   // TSTEPS*FREQ = 1280
    if (idx < TSTEPS * FREQ) {
        int t = idx / FREQ, f = idx % FREQ;
        float fr = (float)f / 10.0f;
        float omega = (6.28318530717958647692f * (float)(t + 1)) * fr;
        d_cosT[idx] = cosf(omega);
        d_sinT[idx] = sinf(omega);
    }
}

// ---------------- phase 1: fused mma.sync GEMM (A converted in-kernel) --------------
#define SA_HI 0
#define SA_LO 5120
#define SB_HI 10240
#define SB_LO 14080
#define STAGE_ELEMS 17920
#define STAGE_BYTES (STAGE_ELEMS * 2)
#define SMEM_GEMM   (2 * STAGE_BYTES)   // 71680 B

__device__ __forceinline__ void load_A(float4* vA, const float* __restrict__ g1,
                                       int kc, int bbase, int t, int tid)
{
    #pragma unroll
    for (int l = 0; l < 8; l++) {
        int idx = tid + l * 128;          // 0..1023 float4 slots
        int row = idx >> 3, g = idx & 7;
        vA[l] = *(const float4*)(g1 +
            ((size_t)(bbase + row) * TSTEPS + t) * INDIM + kc * 32 + g * 4);
    }
}

__device__ __forceinline__ void cvt_sts_A(__nv_bfloat16* sm, int s,
                                          const float4* vA, int tid)
{
    __nv_bfloat16* base = sm + s * STAGE_ELEMS;
    #pragma unroll
    for (int l = 0; l < 8; l++) {
        int idx = tid + l * 128;
        int row = idx >> 3, g = idx & 7;
        float xs[4] = {vA[l].x, vA[l].y, vA[l].z, vA[l].w};
        __nv_bfloat16 h[4], lo[4];
        #pragma unroll
        for (int i = 0; i < 4; i++) {
            h[i]  = __float2bfloat16(xs[i]);
            lo[i] = __float2bfloat16(xs[i] - __bfloat162float(h[i]));
        }
        uint32_t hi01 = (uint32_t)__bfloat16_as_ushort(h[0])  | ((uint32_t)__bfloat16_as_ushort(h[1])  << 16);
        uint32_t hi23 = (uint32_t)__bfloat16_as_ushort(h[2])  | ((uint32_t)__bfloat16_as_ushort(h[3])  << 16);
        uint32_t lo01 = (uint32_t)__bfloat16_as_ushort(lo[0]) | ((uint32_t)__bfloat16_as_ushort(lo[1]) << 16);
        uint32_t lo23 = (uint32_t)__bfloat16_as_ushort(lo[2]) | ((uint32_t)__bfloat16_as_ushort(lo[3]) << 16);
        *(uint2*)(base + SA_HI + row * 40 + g * 4) = make_uint2(hi01, hi23);
        *(uint2*)(base + SA_LO + row * 40 + g * 4) = make_uint2(lo01, lo23);
    }
}

__device__ __forceinline__ void issue_B(__nv_bfloat16* sm, int s, int kc,
                                        int n0, int tid)
{
    __nv_bfloat16* base = sm + s * STAGE_ELEMS;
    #pragma unroll
    for (int l = 0; l < 3; l++) {            // B: 384 chunks (hi+lo pairs)
        int idx = tid + l * 128;
        int row = idx >> 2, g = idx & 3;
        size_t goff = (size_t)(n0 + row) * INDIM + kc * 32 + g * 8;
        cp16(smem_u32(base + SB_HI + row * 40 + g * 8), d_Bhi + goff);
        cp16(smem_u32(base + SB_LO + row * 40 + g * 8), d_Blo + goff);
    }
    CP_COMMIT();
}

__global__ __launch_bounds__(128) void gemm_mma_kernel(const float* __restrict__ g1)
{
    extern __shared__ __align__(16) __nv_bfloat16 sm[];

    const int tid  = threadIdx.x;
    const int lane = tid & 31;
    const int wid  = tid >> 5;
    const int n0   = blockIdx.x * 96;
    const int M0   = blockIdx.y * 128;
    const int t     = M0 >> 10;       // BM=128 divides BSZ -> t constant per block
    const int bbase = M0 & 1023;
    const int wm = (wid & 1) * 64;
    const int wn = (wid >> 1) * 48;

    float d[4][6][4];
    #pragma unroll
    for (int tm = 0; tm < 4; tm++)
        #pragma unroll
        for (int tn = 0; tn < 6; tn++)
            #pragma unroll
            for (int q = 0; q < 4; q++) d[tm][tn][q] = 0.f;

    const int rowA = wm + (lane & 15);
    const int colA = (lane >> 4) * 8;
    const uint32_t relAhi = (uint32_t)(SA_HI + rowA * 40 + colA) * 2;
    const uint32_t relAlo = (uint32_t)(SA_LO + rowA * 40 + colA) * 2;
    const int rowB = wn + ((lane >> 4) * 8) + (lane & 7);
    const int colB = ((lane >> 3) & 1) * 8;
    const uint32_t relBhi = (uint32_t)(SB_HI + rowB * 40 + colB) * 2;
    const uint32_t relBlo = (uint32_t)(SB_LO + rowB * 40 + colB) * 2;
    const uint32_t smbase = smem_u32(sm);

    float4 vA[8];
    load_A(vA, g1, 0, bbase, t, tid);
    cvt_sts_A(sm, 0, vA, tid);
    issue_B(sm, 0, 0, n0, tid);
    load_A(vA, g1, 1, bbase, t, tid);

    for (int kc = 0; kc < 8; kc++) {
        int cur = kc & 1;
        if (kc < 7) {
            cvt_sts_A(sm, cur ^ 1, vA, tid);
            issue_B(sm, cur ^ 1, kc + 1, n0, tid);
            if (kc < 6) load_A(vA, g1, kc + 2, bbase, t, tid);
            CP_WAIT(1);
        } else {
            CP_WAIT(0);
        }
        __syncthreads();

        uint32_t sb = smbase + (uint32_t)cur * STAGE_BYTES;
        #pragma unroll
        for (int ks = 0; ks < 2; ks++) {
            uint32_t ah[4][4], al[4][4], bh[3][4], bl[3][4];
            #pragma unroll
            for (int tm = 0; tm < 4; tm++) {
                uint32_t off = (uint32_t)(tm * 16 * 40 + ks * 16) * 2;
                LDSM4(ah[tm][0], ah[tm][1], ah[tm][2], ah[tm][3], sb + relAhi + off);
                LDSM4(al[tm][0], al[tm][1], al[tm][2], al[tm][3], sb + relAlo + off);
            }
            #pragma unroll
            for (int jB = 0; jB < 3; jB++) {
                uint32_t off = (uint32_t)(jB * 16 * 40 + ks * 16) * 2;
                LDSM4(bh[jB][0], bh[jB][1], bh[jB][2], bh[jB][3], sb + relBhi + off);
                LDSM4(bl[jB][0], bl[jB][1], bl[jB][2], bl[jB][3], sb + relBlo + off);
            }
            #pragma unroll
            for (int tm = 0; tm < 4; tm++)
                #pragma unroll
                for (int tn = 0; tn < 6; tn++) {
                    int jB = tn >> 1, hh = (tn & 1) * 2;
                    MMA16816(d[tm][tn], ah[tm], bh[jB][hh], bh[jB][hh + 1]);
                    MMA16816(d[tm][tn], ah[tm], bl[jB][hh], bl[jB][hh + 1]);
                    MMA16816(d[tm][tn], al[tm], bh[jB][hh], bh[jB][hh + 1]);
                }
        }
        __syncthreads();
    }

    const int mrow = lane >> 2;
    const int ncol = (lane & 3) * 2;
    #pragma unroll
    for (int tn = 0; tn < 6; tn++) {
        int n = n0 + wn + tn * 8 + ncol;
        if (n < NW) {
            float2 bb = *(const float2*)(d_bpack + n);
            #pragma unroll
            for (int tm = 0; tm < 4; tm++) {
                size_t m = (size_t)M0 + wm + tm * 16 + mrow;
                float2 v0 = make_float2(d[tm][tn][0] + bb.x, d[tm][tn][1] + bb.y);
                float2 v1 = make_float2(d[tm][tn][2] + bb.x, d[tm][tn][3] + bb.y);
                *(float2*)(d_pre + m * NW + n)       = v0;
                *(float2*)(d_pre + (m + 8) * NW + n) = v1;
            }
        }
    }
}

// ---------------- phase 2: sequential scan (R11 structure + tanh.approx) ------------
__global__ __launch_bounds__(64, 6) void recurrent_kernel(
    const float* __restrict__ U_a, const float* __restrict__ b_a,
    const float* __restrict__ W_p, const float* __restrict__ b_p,
    const float* __restrict__ fc_w, const float* __restrict__ fc_b,
    float* __restrict__ out)
{
    const int j  = threadIdx.x;
    const int b0 = blockIdx.x * NB;

    __shared__ __align__(16) float sh_h0[HID];
    __shared__ __align__(16) float sh_h1[HID];
    __shared__ u64 sh_freP[FREQ];
    __shared__ float sh_ct[FREQ], sh_st[FREQ];
    __shared__ float2 sh_red[2];

    const float4* U0 = (const float4*)d_Upk;
    const float4* U1 = (const float4*)d_Upk + 1024;
    const float4* U2 = (const float4*)d_Upk + 2048;
    const float4* U3 = (const float4*)d_Upk + 3072;
    const float4* UF = (const float4*)d_Ufpk;
    const float4* H0 = (const float4*)sh_h0;
    const float4* H1 = (const float4*)sh_h1;

    u64 SreP[FREQ], SimP[FREQ];
    #pragma unroll
    for (int f = 0; f < FREQ; f++) { SreP[f] = 0ull; SimP[f] = 0ull; }

    float ua[FREQ];
    #pragma unroll
    for (int f = 0; f < FREQ; f++) ua[f] = U_a[f];
    const float ba = b_a[j];

    sh_h0[j] = 0.f; sh_h1[j] = 0.f;
    __syncthreads();

    float hn0 = 0.f, hn1 = 0.f;

    for (int t = 0; t < TSTEPS; t++) {
        const float* r = d_pre + ((size_t)t * BSZ + b0) * NW;
        float pi0 = r[j],        pi1 = r[NW + j];
        float ps0 = r[64 + j],   ps1 = r[NW + 64 + j];
        float pc0 = r[138 + j],  pc1 = r[NW + 138 + j];
        float po0 = r[202 + j],  po1 = r[NW + 202 + j];

        float ai0 = 0.f, ai1 = 0.f, as0 = 0.f, as1 = 0.f;
        float ac0 = 0.f, ac1 = 0.f, ao0 = 0.f, ao1 = 0.f;

        #pragma unroll
        for (int k4 = 0; k4 < 16; k4++) {
            float4 h0 = H0[k4];
            float4 h1 = H1[k4];
            float4 u;
            u = U0[k4 * 64 + j];
            ai0 = fmaf(h0.x,u.x,ai0); ai0 = fmaf(h0.y,u.y,ai0);
            ai0 = fmaf(h0.z,u.z,ai0); ai0 = fmaf(h0.w,u.w,ai0);
            ai1 = fmaf(h1.x,u.x,ai1); ai1 = fmaf(h1.y,u.y,ai1);
            ai1 = fmaf(h1.z,u.z,ai1); ai1 = fmaf(h1.w,u.w,ai1);
            u = U1[k4 * 64 + j];
            as0 = fmaf(h0.x,u.x,as0); as0 = fmaf(h0.y,u.y,as0);
            as0 = fmaf(h0.z,u.z,as0); as0 = fmaf(h0.w,u.w,as0);
            as1 = fmaf(h1.x,u.x,as1); as1 = fmaf(h1.y,u.y,as1);
            as1 = fmaf(h1.z,u.z,as1); as1 = fmaf(h1.w,u.w,as1);
            u = U2[k4 * 64 + j];
            ac0 = fmaf(h0.x,u.x,ac0); ac0 = fmaf(h0.y,u.y,ac0);
            ac0 = fmaf(h0.z,u.z,ac0); ac0 = fmaf(h0.w,u.w,ac0);
            ac1 = fmaf(h1.x,u.x,ac1); ac1 = fmaf(h1.y,u.y,ac1);
            ac1 = fmaf(h1.z,u.z,ac1); ac1 = fmaf(h1.w,u.w,ac1);
            u = U3[k4 * 64 + j];
            ao0 = fmaf(h0.x,u.x,ao0); ao0 = fmaf(h0.y,u.y,ao0);
            ao0 = fmaf(h0.z,u.z,ao0); ao0 = fmaf(h0.w,u.w,ao0);
            ao1 = fmaf(h1.x,u.x,ao1); ao1 = fmaf(h1.y,u.y,ao1);
            ao1 = fmaf(h1.z,u.z,ao1); ao1 = fmaf(h1.w,u.w,ao1);
        }

        if (j < FREQ) {
            float pf0 = r[128 + j], pf1 = r[NW + 128 + j];
            float af0 = 0.f, af1 = 0.f;
            #pragma unroll
            for (int k4 = 0; k4 < 16; k4++) {
                float4 h0 = H0[k4];
                float4 h1 = H1[k4];
                float4 u = UF[k4 * FREQ + j];
                af0 = fmaf(h0.x,u.x,af0); af0 = fmaf(h0.y,u.y,af0);
                af0 = fmaf(h0.z,u.z,af0); af0 = fmaf(h0.w,u.w,af0);
                af1 = fmaf(h1.x,u.x,af1); af1 = fmaf(h1.y,u.y,af1);
                af1 = fmaf(h1.z,u.z,af1); af1 = fmaf(h1.w,u.w,af1);
            }
            sh_freP[j] = pack2f(hsig(pf0 + af0), hsig(pf1 + af1));
            sh_ct[j] = d_cosT[t * FREQ + j];
            sh_st[j] = d_sinT[t * FREQ + j];
        }

        float gi0 = hsig(pi0 + ai0), gi1 = hsig(pi1 + ai1);
        float gs0 = hsig(ps0 + as0), gs1 = hsig(ps1 + as1);
        float cc0 = gi0 * tanh_fast(pc0 + ac0), cc1 = gi1 * tanh_fast(pc1 + ac1);
        float go0 = hsig(po0 + ao0), go1 = hsig(po1 + ao1);

        __syncthreads();   // A: sh_freP/ct/st visible; all sh_h reads done

        u64 ccP = pack2f(cc0, cc1);
        u64 gsP = pack2f(gs0, gs1);
        u64 aaP = pack2f(ba, ba);
        #pragma unroll
        for (int f = 0; f < FREQ; f++) {
            u64 ctd = dup2f(sh_ct[f]);
            u64 std = dup2f(sh_st[f]);
            u64 frP = mul2(gsP, sh_freP[f]);
            SreP[f] = fma2(frP, SreP[f], mul2(ccP, ctd));
            SimP[f] = fma2(frP, SimP[f], mul2(ccP, std));
            u64 ampP = fma2(SimP[f], SimP[f], mul2(SreP[f], SreP[f]));
            aaP = fma2(ampP, dup2f(ua[f]), aaP);
        }

        float2 a2 = unpack2f(aaP);
        hn0 = go0 * tanh_fast(a2.x);
        hn1 = go1 * tanh_fast(a2.y);
        sh_h0[j] = hn0;    // safe: all sh_h reads happened before barrier A
        sh_h1[j] = hn1;
        __syncthreads();   // B: h(t+1) visible for next iteration
    }

    float vv = 0.f;
    #pragma unroll
    for (int o = 0; o < OUTD; o++) vv = fmaf(W_p[j * OUTD + o], fc_w[o], vv);
    u64 pP = mul2(pack2f(hn0, hn1), dup2f(vv));
    #pragma unroll
    for (int off = 16; off > 0; off >>= 1)
        pP = add2(pP, __shfl_down_sync(0xffffffffu, pP, off));
    if ((j & 31) == 0) sh_red[j >> 5] = unpack2f(pP);
    __syncthreads();
    if (j == 0) {
        float s0 = fc_b[0];
        #pragma unroll
        for (int o = 0; o < OUTD; o++) s0 = fmaf(b_p[o], fc_w[o], s0);
        out[b0 + 0] = s0 + sh_red[0].x + sh_red[1].x;
        out[b0 + 1] = s0 + sh_red[0].y + sh_red[1].y;
    }
}

extern "C" void kernel_launch(void* const* d_in, const int* in_sizes, int n_in,
                              void* d_out, int out_size)
{
    const float* g1    = (const float*)d_in[0];
    const float* W_i   = (const float*)d_in[1];
    const float* U_i   = (const float*)d_in[2];
    const float* b_i   = (const float*)d_in[3];
    const float* W_ste = (const float*)d_in[4];
    const float* U_ste = (const float*)d_in[5];
    const float* b_ste = (const float*)d_in[6];
    const float* W_fre = (const float*)d_in[7];
    const float* U_fre = (const float*)d_in[8];
    const float* b_fre = (const float*)d_in[9];
    const float* W_c   = (const float*)d_in[10];
    const float* U_c   = (const float*)d_in[11];
    const float* b_c   = (const float*)d_in[12];
    const float* W_o   = (const float*)d_in[13];
    const float* U_o   = (const float*)d_in[14];
    const float* b_o   = (const float*)d_in[15];
    const float* U_a   = (const float*)d_in[16];
    const float* b_a   = (const float*)d_in[17];
    const float* W_p   = (const float*)d_in[18];
    const float* b_p   = (const float*)d_in[19];
    const float* fc_w  = (const float*)d_in[20];
    const float* fc_b  = (const float*)d_in[21];

    cudaFuncSetAttribute(gemm_mma_kernel,
                         cudaFuncAttributeMaxDynamicSharedMemorySize, SMEM_GEMM);

    pack_w_kernel<<<NPAD, 256>>>(W_i, b_i, W_ste, b_ste, W_fre, b_fre,
                                 W_c, b_c, W_o, b_o);
    pack_u_kernel<<<16, 256>>>(U_i, U_ste, U_c, U_o, U_fre);
    trig_kernel<<<5, 256>>>();
    gemm_mma_kernel<<<dim3(3, 1024), 128, SMEM_GEMM>>>(g1);
    recurrent_kernel<<<BSZ / NB, HID>>>(U_a, b_a, W_p, b_p, fc_w, fc_b,
                                        (float*)d_out);
}

// round 14
// speedup vs baseline: 1.1064x; 1.1064x over previous
#include <cuda_runtime.h>
#include <cuda_bf16.h>
#include <cstdint>

#define BSZ    1024
#define TSTEPS 128
#define INDIM  256
#define HID    64
#define FREQ   10
#define OUTD   16
#define NW     266     // packed gate cols: i(64) | ste(64) | fre(10) | c(64) | o(64)
#define NPAD   288     // padded N: 3 tiles of 96
#define MROWS  (BSZ * TSTEPS)
#define NB     4       // batch elements per recurrent block (2 f32x2 pairs)

typedef unsigned long long u64;

// ----------------- device globals (no runtime allocation) -----------------
__device__ __align__(16) float d_pre[(size_t)MROWS * NW];      // (t*1024+b, 266) fp32
__device__ __align__(16) __nv_bfloat16 d_Bhi[NPAD * INDIM];    // [n][k] bf16 hi
__device__ __align__(16) __nv_bfloat16 d_Blo[NPAD * INDIM];    // [n][k] bf16 lo
__device__ __align__(8)  float d_bpack[NPAD];
__device__ float d_Upk[4 * HID * HID];                          // interleaved [m][k4][j][kk]
__device__ float d_Ufpk[16 * FREQ * 4];
__device__ float d_cosT[TSTEPS * FREQ];
__device__ float d_sinT[TSTEPS * FREQ];

__device__ __forceinline__ float hsig(float x) {
    return fminf(fmaxf(x * (1.0f / 6.0f) + 0.5f, 0.0f), 1.0f);
}

// ---- packed f32x2 helpers (state update only) ----
__device__ __forceinline__ u64 pack2f(float lo, float hi) {
    u64 r; asm("mov.b64 %0, {%1, %2};" : "=l"(r) : "f"(lo), "f"(hi)); return r;
}
__device__ __forceinline__ float2 unpack2f(u64 v) {
    float2 r; asm("mov.b64 {%0, %1}, %2;" : "=f"(r.x), "=f"(r.y) : "l"(v)); return r;
}
__device__ __forceinline__ u64 dup2f(float x) { return pack2f(x, x); }
__device__ __forceinline__ u64 fma2(u64 a, u64 b, u64 c) {
    u64 d; asm("fma.rn.f32x2 %0, %1, %2, %3;" : "=l"(d) : "l"(a), "l"(b), "l"(c)); return d;
}
__device__ __forceinline__ u64 mul2(u64 a, u64 b) {
    u64 d; asm("mul.rn.f32x2 %0, %1, %2;" : "=l"(d) : "l"(a), "l"(b)); return d;
}
__device__ __forceinline__ u64 add2(u64 a, u64 b) {
    u64 d; asm("add.rn.f32x2 %0, %1, %2;" : "=l"(d) : "l"(a), "l"(b)); return d;
}

__device__ __forceinline__ uint32_t smem_u32(const void* p) {
    uint32_t a;
    asm("{ .reg .u64 t; cvta.to.shared.u64 t, %1; cvt.u32.u64 %0, t; }" : "=r"(a) : "l"(p));
    return a;
}

// ---- base-ISA async copy / mma helpers (no sm_103a-only features) ----
__device__ __forceinline__ void cp16(uint32_t dst, const void* src) {
    asm volatile("cp.async.cg.shared.global [%0], [%1], 16;" :: "r"(dst), "l"(src));
}
#define CP_COMMIT()  asm volatile("cp.async.commit_group;" ::: "memory")
#define CP_WAIT(N)   asm volatile("cp.async.wait_group %0;" :: "n"(N) : "memory")

#define LDSM4(r0, r1, r2, r3, addr) \
    asm volatile("ldmatrix.sync.aligned.m8n8.x4.shared.b16 {%0,%1,%2,%3}, [%4];" \
        : "=r"(r0), "=r"(r1), "=r"(r2), "=r"(r3) : "r"(addr))

#define MMA16816(d, a, b0, b1) \
    asm volatile("mma.sync.aligned.m16n8k16.row.col.f32.bf16.bf16.f32 " \
        "{%0,%1,%2,%3}, {%4,%5,%6,%7}, {%8,%9}, {%0,%1,%2,%3};" \
        : "+f"((d)[0]), "+f"((d)[1]), "+f"((d)[2]), "+f"((d)[3]) \
        : "r"((a)[0]), "r"((a)[1]), "r"((a)[2]), "r"((a)[3]), "r"(b0), "r"(b1))

// ---------------- pack W_* -> Bhi/Blo [288][256] bf16 (+ biases fp32) ---------------
__global__ void pack_w_kernel(const float* __restrict__ W_i,  const float* __restrict__ b_i,
                              const float* __restrict__ W_ste,const float* __restrict__ b_ste,
                              const float* __restrict__ W_fre,const float* __restrict__ b_fre,
                              const float* __restrict__ W_c,  const float* __restrict__ b_c,
                              const float* __restrict__ W_o,  const float* __restrict__ b_o)
{
    int n = blockIdx.x;      // 0..287
    int k = threadIdx.x;     // 0..255
    float w = 0.f, bias = 0.f;
    if (n < 64)       { w = W_i  [k * HID  + n];         bias = b_i  [n]; }
    else if (n < 128) { w = W_ste[k * HID  + (n - 64)];  bias = b_ste[n - 64]; }
    else if (n < 138) { w = W_fre[k * FREQ + (n - 128)]; bias = b_fre[n - 128]; }
    else if (n < 202) { w = W_c  [k * HID  + (n - 138)]; bias = b_c  [n - 138]; }
    else if (n < 266) { w = W_o  [k * HID  + (n - 202)]; bias = b_o  [n - 202]; }
    __nv_bfloat16 h = __float2bfloat16(w);
    __nv_bfloat16 l = __float2bfloat16(w - __bfloat162float(h));
    d_Bhi[n * INDIM + k] = h;
    d_Blo[n * INDIM + k] = l;
    if (k == 0) d_bpack[n] = bias;
}

// -------- interleave U so thread j's float4 = U[4*k4 .. 4*k4+3][j] (warp = 512B) ----
__global__ void pack_u_kernel(const float* __restrict__ U_i, const float* __restrict__ U_ste,
                              const float* __restrict__ U_c, const float* __restrict__ U_o,
                              const float* __restrict__ U_fre)
{
    int idx = blockIdx.x * blockDim.x + threadIdx.x;   // 16 x 256 = 4096
    int k4 = idx >> 8, j = (idx >> 2) & 63, kk = idx & 3;
    int k = 4 * k4 + kk;
    d_Upk[0 * 4096 + idx] = U_i  [k * HID + j];
    d_Upk[1 * 4096 + idx] = U_ste[k * HID + j];
    d_Upk[2 * 4096 + idx] = U_c  [k * HID + j];
    d_Upk[3 * 4096 + idx] = U_o  [k * HID + j];
    if (idx < 16 * FREQ * 4) {
        int fk4 = idx / (FREQ * 4), rr = idx % (FREQ * 4);
        int fj = rr >> 2, fkk = rr & 3;
        d_Ufpk[idx] = U_fre[(4 * fk4 + fkk) * FREQ + fj];
    }
}

// ---------------- trig table, replicating reference fp32 arithmetic ------------------
__global__ void trig_kernel()
{
    int idx = blockIdx.x * blockDim.x + threadIdx.x;   // TSTEPS*FREQ = 1280
    if (idx < TSTEPS * FREQ) {
        int t = idx / FREQ, f = idx % FREQ;
        float fr = (float)f / 10.0f;
        float omega = (6.28318530717958647692f * (float)(t + 1)) * fr;
        d_cosT[idx] = cosf(omega);
        d_sinT[idx] = sinf(omega);
    }
}

// ---------------- phase 1: fused mma.sync GEMM (A converted in-kernel) --------------
#define SA_HI 0
#define SA_LO 5120
#define SB_HI 10240
#define SB_LO 14080
#define STAGE_ELEMS 17920
#define STAGE_BYTES (STAGE_ELEMS * 2)
#define SMEM_GEMM   (2 * STAGE_BYTES)   // 71680 B

__device__ __forceinline__ void load_A(float4* vA, const float* __restrict__ g1,
                                       int kc, int bbase, int t, int tid)
{
    #pragma unroll
    for (int l = 0; l < 8; l++) {
        int idx = tid + l * 128;          // 0..1023 float4 slots
        int row = idx >> 3, g = idx & 7;
        vA[l] = *(const float4*)(g1 +
            ((size_t)(bbase + row) * TSTEPS + t) * INDIM + kc * 32 + g * 4);
    }
}

__device__ __forceinline__ void cvt_sts_A(__nv_bfloat16* sm, int s,
                                          const float4* vA, int tid)
{
    __nv_bfloat16* base = sm + s * STAGE_ELEMS;
    #pragma unroll
    for (int l = 0; l < 8; l++) {
        int idx = tid + l * 128;
        int row = idx >> 3, g = idx & 7;
        float xs[4] = {vA[l].x, vA[l].y, vA[l].z, vA[l].w};
        __nv_bfloat16 h[4], lo[4];
        #pragma unroll
        for (int i = 0; i < 4; i++) {
            h[i]  = __float2bfloat16(xs[i]);
            lo[i] = __float2bfloat16(xs[i] - __bfloat162float(h[i]));
        }
        uint32_t hi01 = (uint32_t)__bfloat16_as_ushort(h[0])  | ((uint32_t)__bfloat16_as_ushort(h[1])  << 16);
        uint32_t hi23 = (uint32_t)__bfloat16_as_ushort(h[2])  | ((uint32_t)__bfloat16_as_ushort(h[3])  << 16);
        uint32_t lo01 = (uint32_t)__bfloat16_as_ushort(lo[0]) | ((uint32_t)__bfloat16_as_ushort(lo[1]) << 16);
        uint32_t lo23 = (uint32_t)__bfloat16_as_ushort(lo[2]) | ((uint32_t)__bfloat16_as_ushort(lo[3]) << 16);
        *(uint2*)(base + SA_HI + row * 40 + g * 4) = make_uint2(hi01, hi23);
        *(uint2*)(base + SA_LO + row * 40 + g * 4) = make_uint2(lo01, lo23);
    }
}

__device__ __forceinline__ void issue_B(__nv_bfloat16* sm, int s, int kc,
                                        int n0, int tid)
{
    __nv_bfloat16* base = sm + s * STAGE_ELEMS;
    #pragma unroll
    for (int l = 0; l < 3; l++) {            // B: 384 chunks (hi+lo pairs)
        int idx = tid + l * 128;
        int row = idx >> 2, g = idx & 3;
        size_t goff = (size_t)(n0 + row) * INDIM + kc * 32 + g * 8;
        cp16(smem_u32(base + SB_HI + row * 40 + g * 8), d_Bhi + goff);
        cp16(smem_u32(base + SB_LO + row * 40 + g * 8), d_Blo + goff);
    }
    CP_COMMIT();
}

__global__ __launch_bounds__(128) void gemm_mma_kernel(const float* __restrict__ g1)
{
    extern __shared__ __align__(16) __nv_bfloat16 sm[];

    const int tid  = threadIdx.x;
    const int lane = tid & 31;
    const int wid  = tid >> 5;
    const int n0   = blockIdx.x * 96;
    const int M0   = blockIdx.y * 128;
    const int t     = M0 >> 10;       // BM=128 divides BSZ -> t constant per block
    const int bbase = M0 & 1023;
    const int wm = (wid & 1) * 64;
    const int wn = (wid >> 1) * 48;

    float d[4][6][4];
    #pragma unroll
    for (int tm = 0; tm < 4; tm++)
        #pragma unroll
        for (int tn = 0; tn < 6; tn++)
            #pragma unroll
            for (int q = 0; q < 4; q++) d[tm][tn][q] = 0.f;

    const int rowA = wm + (lane & 15);
    const int colA = (lane >> 4) * 8;
    const uint32_t relAhi = (uint32_t)(SA_HI + rowA * 40 + colA) * 2;
    const uint32_t relAlo = (uint32_t)(SA_LO + rowA * 40 + colA) * 2;
    const int rowB = wn + ((lane >> 4) * 8) + (lane & 7);
    const int colB = ((lane >> 3) & 1) * 8;
    const uint32_t relBhi = (uint32_t)(SB_HI + rowB * 40 + colB) * 2;
    const uint32_t relBlo = (uint32_t)(SB_LO + rowB * 40 + colB) * 2;
    const uint32_t smbase = smem_u32(sm);

    float4 vA[8];
    load_A(vA, g1, 0, bbase, t, tid);
    cvt_sts_A(sm, 0, vA, tid);
    issue_B(sm, 0, 0, n0, tid);
    load_A(vA, g1, 1, bbase, t, tid);

    for (int kc = 0; kc < 8; kc++) {
        int cur = kc & 1;
        if (kc < 7) {
            cvt_sts_A(sm, cur ^ 1, vA, tid);
            issue_B(sm, cur ^ 1, kc + 1, n0, tid);
            if (kc < 6) load_A(vA, g1, kc + 2, bbase, t, tid);
            CP_WAIT(1);
        } else {
            CP_WAIT(0);
        }
        __syncthreads();

        uint32_t sb = smbase + (uint32_t)cur * STAGE_BYTES;
        #pragma unroll
        for (int ks = 0; ks < 2; ks++) {
            uint32_t ah[4][4], al[4][4], bh[3][4], bl[3][4];
            #pragma unroll
            for (int tm = 0; tm < 4; tm++) {
                uint32_t off = (uint32_t)(tm * 16 * 40 + ks * 16) * 2;
                LDSM4(ah[tm][0], ah[tm][1], ah[tm][2], ah[tm][3], sb + relAhi + off);
                LDSM4(al[tm][0], al[tm][1], al[tm][2], al[tm][3], sb + relAlo + off);
            }
            #pragma unroll
            for (int jB = 0; jB < 3; jB++) {
                uint32_t off = (uint32_t)(jB * 16 * 40 + ks * 16) * 2;
                LDSM4(bh[jB][0], bh[jB][1], bh[jB][2], bh[jB][3], sb + relBhi + off);
                LDSM4(bl[jB][0], bl[jB][1], bl[jB][2], bl[jB][3], sb + relBlo + off);
            }
            #pragma unroll
            for (int tm = 0; tm < 4; tm++)
                #pragma unroll
                for (int tn = 0; tn < 6; tn++) {
                    int jB = tn >> 1, hh = (tn & 1) * 2;
                    MMA16816(d[tm][tn], ah[tm], bh[jB][hh], bh[jB][hh + 1]);
                    MMA16816(d[tm][tn], ah[tm], bl[jB][hh], bl[jB][hh + 1]);
                    MMA16816(d[tm][tn], al[tm], bh[jB][hh], bh[jB][hh + 1]);
                }
        }
        __syncthreads();
    }

    const int mrow = lane >> 2;
    const int ncol = (lane & 3) * 2;
    #pragma unroll
    for (int tn = 0; tn < 6; tn++) {
        int n = n0 + wn + tn * 8 + ncol;
        if (n < NW) {
            float2 bb = *(const float2*)(d_bpack + n);
            #pragma unroll
            for (int tm = 0; tm < 4; tm++) {
                size_t m = (size_t)M0 + wm + tm * 16 + mrow;
                float2 v0 = make_float2(d[tm][tn][0] + bb.x, d[tm][tn][1] + bb.y);
                float2 v1 = make_float2(d[tm][tn][2] + bb.x, d[tm][tn][3] + bb.y);
                *(float2*)(d_pre + m * NW + n)       = v0;
                *(float2*)(d_pre + (m + 8) * NW + n) = v1;
            }
        }
    }
}

// ---------------- phase 2: scan, NB=4 batches/block (halves per-batch U traffic) ----
// Scalar-FFMA GEMV over 4 batches per U load; f32x2 state update on 2 pairs.
__global__ __launch_bounds__(64, 4) void recurrent_kernel(
    const float* __restrict__ U_a, const float* __restrict__ b_a,
    const float* __restrict__ W_p, const float* __restrict__ b_p,
    const float* __restrict__ fc_w, const float* __restrict__ fc_b,
    float* __restrict__ out)
{
    const int j  = threadIdx.x;
    const int b0 = blockIdx.x * NB;

    __shared__ __align__(16) float sh_h[NB][HID];
    __shared__ u64 sh_freP[2][FREQ];      // pair 0 = (b0,b1), pair 1 = (b2,b3)
    __shared__ float sh_ct[FREQ], sh_st[FREQ];
    __shared__ float2 sh_red[2][2];       // [warp][pair]

    const float4* U0 = (const float4*)d_Upk;
    const float4* U1 = (const float4*)d_Upk + 1024;
    const float4* U2 = (const float4*)d_Upk + 2048;
    const float4* U3 = (const float4*)d_Upk + 3072;
    const float4* UF = (const float4*)d_Ufpk;

    u64 Sre[2][FREQ], Sim[2][FREQ];
    #pragma unroll
    for (int p = 0; p < 2; p++)
        #pragma unroll
        for (int f = 0; f < FREQ; f++) { Sre[p][f] = 0ull; Sim[p][f] = 0ull; }

    float ua[FREQ];
    #pragma unroll
    for (int f = 0; f < FREQ; f++) ua[f] = U_a[f];
    const float ba = b_a[j];

    #pragma unroll
    for (int b = 0; b < NB; b++) sh_h[b][j] = 0.f;
    __syncthreads();

    float hn[NB] = {0.f, 0.f, 0.f, 0.f};

    for (int t = 0; t < TSTEPS; t++) {
        const float* r = d_pre + ((size_t)t * BSZ + b0) * NW;
        float pi[NB], ps[NB], pc[NB], po[NB];
        #pragma unroll
        for (int b = 0; b < NB; b++) {
            pi[b] = r[b * NW + j];
            ps[b] = r[b * NW + 64 + j];
            pc[b] = r[b * NW + 138 + j];
            po[b] = r[b * NW + 202 + j];
        }

        float ai[NB] = {0,0,0,0}, as_[NB] = {0,0,0,0};
        float ac[NB] = {0,0,0,0}, ao[NB] = {0,0,0,0};

        #pragma unroll 4
        for (int k4 = 0; k4 < 16; k4++) {
            float4 h[NB];
            #pragma unroll
            for (int b = 0; b < NB; b++)
                h[b] = ((const float4*)sh_h[b])[k4];
            float4 u;
            u = U0[k4 * 64 + j];
            #pragma unroll
            for (int b = 0; b < NB; b++) {
                ai[b] = fmaf(h[b].x,u.x,ai[b]); ai[b] = fmaf(h[b].y,u.y,ai[b]);
                ai[b] = fmaf(h[b].z,u.z,ai[b]); ai[b] = fmaf(h[b].w,u.w,ai[b]);
            }
            u = U1[k4 * 64 + j];
            #pragma unroll
            for (int b = 0; b < NB; b++) {
                as_[b] = fmaf(h[b].x,u.x,as_[b]); as_[b] = fmaf(h[b].y,u.y,as_[b]);
                as_[b] = fmaf(h[b].z,u.z,as_[b]); as_[b] = fmaf(h[b].w,u.w,as_[b]);
            }
            u = U2[k4 * 64 + j];
            #pragma unroll
            for (int b = 0; b < NB; b++) {
                ac[b] = fmaf(h[b].x,u.x,ac[b]); ac[b] = fmaf(h[b].y,u.y,ac[b]);
                ac[b] = fmaf(h[b].z,u.z,ac[b]); ac[b] = fmaf(h[b].w,u.w,ac[b]);
            }
            u = U3[k4 * 64 + j];
            #pragma unroll
            for (int b = 0; b < NB; b++) {
                ao[b] = fmaf(h[b].x,u.x,ao[b]); ao[b] = fmaf(h[b].y,u.y,ao[b]);
                ao[b] = fmaf(h[b].z,u.z,ao[b]); ao[b] = fmaf(h[b].w,u.w,ao[b]);
            }
        }

        if (j < FREQ) {
            float pf[NB], af[NB] = {0,0,0,0};
            #pragma unroll
            for (int b = 0; b < NB; b++) pf[b] = r[b * NW + 128 + j];
            #pragma unroll 4
            for (int k4 = 0; k4 < 16; k4++) {
                float4 u = UF[k4 * FREQ + j];
                #pragma unroll
                for (int b = 0; b < NB; b++) {
                    float4 h = ((const float4*)sh_h[b])[k4];
                    af[b] = fmaf(h.x,u.x,af[b]); af[b] = fmaf(h.y,u.y,af[b]);
                    af[b] = fmaf(h.z,u.z,af[b]); af[b] = fmaf(h.w,u.w,af[b]);
                }
            }
            sh_freP[0][j] = pack2f(hsig(pf[0] + af[0]), hsig(pf[1] + af[1]));
            sh_freP[1][j] = pack2f(hsig(pf[2] + af[2]), hsig(pf[3] + af[3]));
            sh_ct[j] = d_cosT[t * FREQ + j];
            sh_st[j] = d_sinT[t * FREQ + j];
        }

        float gi[NB], gs[NB], cc[NB], go[NB];
        #pragma unroll
        for (int b = 0; b < NB; b++) {
            gi[b] = hsig(pi[b] + ai[b]);
            gs[b] = hsig(ps[b] + as_[b]);
            cc[b] = gi[b] * tanhf(pc[b] + ac[b]);
            go[b] = hsig(po[b] + ao[b]);
        }

        __syncthreads();   // A: sh_freP/ct/st visible; all sh_h reads done

        u64 ccP[2] = { pack2f(cc[0], cc[1]), pack2f(cc[2], cc[3]) };
        u64 gsP[2] = { pack2f(gs[0], gs[1]), pack2f(gs[2], gs[3]) };
        u64 aaP[2] = { pack2f(ba, ba), pack2f(ba, ba) };
        #pragma unroll
        for (int f = 0; f < FREQ; f++) {
            u64 ctd = dup2f(sh_ct[f]);
            u64 std = dup2f(sh_st[f]);
            u64 uad = dup2f(ua[f]);
            #pragma unroll
            for (int p = 0; p < 2; p++) {
                u64 frP = mul2(gsP[p], sh_freP[p][f]);
                Sre[p][f] = fma2(frP, Sre[p][f], mul2(ccP[p], ctd));
                Sim[p][f] = fma2(frP, Sim[p][f], mul2(ccP[p], std));
                u64 ampP = fma2(Sim[p][f], Sim[p][f], mul2(Sre[p][f], Sre[p][f]));
                aaP[p] = fma2(ampP, uad, aaP[p]);
            }
        }

        float2 a0 = unpack2f(aaP[0]);
        float2 a1 = unpack2f(aaP[1]);
        hn[0] = go[0] * tanhf(a0.x);
        hn[1] = go[1] * tanhf(a0.y);
        hn[2] = go[2] * tanhf(a1.x);
        hn[3] = go[3] * tanhf(a1.y);
        #pragma unroll
        for (int b = 0; b < NB; b++) sh_h[b][j] = hn[b];  // reads done before barrier A
        __syncthreads();   // B: h(t+1) visible for next iteration
    }

    float vv = 0.f;
    #pragma unroll
    for (int o = 0; o < OUTD; o++) vv = fmaf(W_p[j * OUTD + o], fc_w[o], vv);
    u64 vd = dup2f(vv);
    u64 p0 = mul2(pack2f(hn[0], hn[1]), vd);
    u64 p1 = mul2(pack2f(hn[2], hn[3]), vd);
    #pragma unroll
    for (int off = 16; off > 0; off >>= 1) {
        p0 = add2(p0, __shfl_down_sync(0xffffffffu, p0, off));
        p1 = add2(p1, __shfl_down_sync(0xffffffffu, p1, off));
    }
    if ((j & 31) == 0) {
        sh_red[j >> 5][0] = unpack2f(p0);
        sh_red[j >> 5][1] = unpack2f(p1);
    }
    __syncthreads();
    if (j == 0) {
        float s0 = fc_b[0];
        #pragma unroll
        for (int o = 0; o < OUTD; o++) s0 = fmaf(b_p[o], fc_w[o], s0);
        out[b0 + 0] = s0 + sh_red[0][0].x + sh_red[1][0].x;
        out[b0 + 1] = s0 + sh_red[0][0].y + sh_red[1][0].y;
        out[b0 + 2] = s0 + sh_red[0][1].x + sh_red[1][1].x;
        out[b0 + 3] = s0 + sh_red[0][1].y + sh_red[1][1].y;
    }
}

extern "C" void kernel_launch(void* const* d_in, const int* in_sizes, int n_in,
                              void* d_out, int out_size)
{
    const float* g1    = (const float*)d_in[0];
    const float* W_i   = (const float*)d_in[1];
    const float* U_i   = (const float*)d_in[2];
    const float* b_i   = (const float*)d_in[3];
    const float* W_ste = (const float*)d_in[4];
    const float* U_ste = (const float*)d_in[5];
    const float* b_ste = (const float*)d_in[6];
    const float* W_fre = (const float*)d_in[7];
    const float* U_fre = (const float*)d_in[8];
    const float* b_fre = (const float*)d_in[9];
    const float* W_c   = (const float*)d_in[10];
    const float* U_c   = (const float*)d_in[11];
    const float* b_c   = (const float*)d_in[12];
    const float* W_o   = (const float*)d_in[13];
    const float* U_o   = (const float*)d_in[14];
    const float* b_o   = (const float*)d_in[15];
    const float* U_a   = (const float*)d_in[16];
    const float* b_a   = (const float*)d_in[17];
    const float* W_p   = (const float*)d_in[18];
    const float* b_p   = (const float*)d_in[19];
    const float* fc_w  = (const float*)d_in[20];
    const float* fc_b  = (const float*)d_in[21];

    cudaFuncSetAttribute(gemm_mma_kernel,
                         cudaFuncAttributeMaxDynamicSharedMemorySize, SMEM_GEMM);

    pack_w_kernel<<<NPAD, 256>>>(W_i, b_i, W_ste, b_ste, W_fre, b_fre,
                                 W_c, b_c, W_o, b_o);
    pack_u_kernel<<<16, 256>>>(U_i, U_ste, U_c, U_o, U_fre);
    trig_kernel<<<5, 256>>>();
    gemm_mma_kernel<<<dim3(3, 1024), 128, SMEM_GEMM>>>(g1);
    recurrent_kernel<<<BSZ / NB, HID>>>(U_a, b_a, W_p, b_p, fc_w, fc_b,
                                        (float*)d_out);
}

// round 15
// speedup vs baseline: 1.1207x; 1.0130x over previous
#include <cuda_runtime.h>
#include <cuda_bf16.h>
#include <cstdint>

#define BSZ    1024
#define TSTEPS 128
#define INDIM  256
#define HID    64
#define FREQ   10
#define OUTD   16
#define NW     266     // packed gate cols: i(64) | ste(64) | fre(10) | c(64) | o(64)
#define NPAD   288     // padded N: 3 tiles of 96
#define MROWS  (BSZ * TSTEPS)
#define NB     4       // batch elements per recurrent block (2 f32x2 pairs)

typedef unsigned long long u64;

// ----------------- device globals (no runtime allocation) -----------------
__device__ __align__(16) float d_pre[(size_t)MROWS * NW];      // (t*1024+b, 266) fp32
__device__ __align__(16) __nv_bfloat16 d_Bhi[NPAD * INDIM];    // [n][k] bf16 hi
__device__ __align__(16) __nv_bfloat16 d_Blo[NPAD * INDIM];    // [n][k] bf16 lo
__device__ __align__(8)  float d_bpack[NPAD];
__device__ float d_Upk[4 * HID * HID];                          // interleaved [m][k4][j][kk]
__device__ float d_Ufpk[16 * FREQ * 4];
__device__ float d_cosT[TSTEPS * FREQ];
__device__ float d_sinT[TSTEPS * FREQ];

__device__ __forceinline__ float hsig(float x) {
    return fminf(fmaxf(x * (1.0f / 6.0f) + 0.5f, 0.0f), 1.0f);
}

// ---- packed f32x2 helpers ----
__device__ __forceinline__ u64 pack2f(float lo, float hi) {
    u64 r; asm("mov.b64 %0, {%1, %2};" : "=l"(r) : "f"(lo), "f"(hi)); return r;
}
__device__ __forceinline__ float2 unpack2f(u64 v) {
    float2 r; asm("mov.b64 {%0, %1}, %2;" : "=f"(r.x), "=f"(r.y) : "l"(v)); return r;
}
__device__ __forceinline__ u64 dup2f(float x) { return pack2f(x, x); }
__device__ __forceinline__ u64 fma2(u64 a, u64 b, u64 c) {
    u64 d; asm("fma.rn.f32x2 %0, %1, %2, %3;" : "=l"(d) : "l"(a), "l"(b), "l"(c)); return d;
}
__device__ __forceinline__ u64 mul2(u64 a, u64 b) {
    u64 d; asm("mul.rn.f32x2 %0, %1, %2;" : "=l"(d) : "l"(a), "l"(b)); return d;
}
__device__ __forceinline__ u64 add2(u64 a, u64 b) {
    u64 d; asm("add.rn.f32x2 %0, %1, %2;" : "=l"(d) : "l"(a), "l"(b)); return d;
}

__device__ __forceinline__ uint32_t smem_u32(const void* p) {
    uint32_t a;
    asm("{ .reg .u64 t; cvta.to.shared.u64 t, %1; cvt.u32.u64 %0, t; }" : "=r"(a) : "l"(p));
    return a;
}

// ---- base-ISA async copy / mma helpers (no sm_103a-only features) ----
__device__ __forceinline__ void cp16(uint32_t dst, const void* src) {
    asm volatile("cp.async.cg.shared.global [%0], [%1], 16;" :: "r"(dst), "l"(src));
}
#define CP_COMMIT()  asm volatile("cp.async.commit_group;" ::: "memory")
#define CP_WAIT(N)   asm volatile("cp.async.wait_group %0;" :: "n"(N) : "memory")

#define LDSM4(r0, r1, r2, r3, addr) \
    asm volatile("ldmatrix.sync.aligned.m8n8.x4.shared.b16 {%0,%1,%2,%3}, [%4];" \
        : "=r"(r0), "=r"(r1), "=r"(r2), "=r"(r3) : "r"(addr))

#define MMA16816(d, a, b0, b1) \
    asm volatile("mma.sync.aligned.m16n8k16.row.col.f32.bf16.bf16.f32 " \
        "{%0,%1,%2,%3}, {%4,%5,%6,%7}, {%8,%9}, {%0,%1,%2,%3};" \
        : "+f"((d)[0]), "+f"((d)[1]), "+f"((d)[2]), "+f"((d)[3]) \
        : "r"((a)[0]), "r"((a)[1]), "r"((a)[2]), "r"((a)[3]), "r"(b0), "r"(b1))

// ---------------- pack W_* -> Bhi/Blo [288][256] bf16 (+ biases fp32) ---------------
__global__ void pack_w_kernel(const float* __restrict__ W_i,  const float* __restrict__ b_i,
                              const float* __restrict__ W_ste,const float* __restrict__ b_ste,
                              const float* __restrict__ W_fre,const float* __restrict__ b_fre,
                              const float* __restrict__ W_c,  const float* __restrict__ b_c,
                              const float* __restrict__ W_o,  const float* __restrict__ b_o)
{
    int n = blockIdx.x;      // 0..287
    int k = threadIdx.x;     // 0..255
    float w = 0.f, bias = 0.f;
    if (n < 64)       { w = W_i  [k * HID  + n];         bias = b_i  [n]; }
    else if (n < 128) { w = W_ste[k * HID  + (n - 64)];  bias = b_ste[n - 64]; }
    else if (n < 138) { w = W_fre[k * FREQ + (n - 128)]; bias = b_fre[n - 128]; }
    else if (n < 202) { w = W_c  [k * HID  + (n - 138)]; bias = b_c  [n - 138]; }
    else if (n < 266) { w = W_o  [k * HID  + (n - 202)]; bias = b_o  [n - 202]; }
    __nv_bfloat16 h = __float2bfloat16(w);
    __nv_bfloat16 l = __float2bfloat16(w - __bfloat162float(h));
    d_Bhi[n * INDIM + k] = h;
    d_Blo[n * INDIM + k] = l;
    if (k == 0) d_bpack[n] = bias;
}

// -------- interleave U so thread j's float4 = U[4*k4 .. 4*k4+3][j] (warp = 512B) ----
__global__ void pack_u_kernel(const float* __restrict__ U_i, const float* __restrict__ U_ste,
                              const float* __restrict__ U_c, const float* __restrict__ U_o,
                              const float* __restrict__ U_fre)
{
    int idx = blockIdx.x * blockDim.x + threadIdx.x;   // 16 x 256 = 4096
    int k4 = idx >> 8, j = (idx >> 2) & 63, kk = idx & 3;
    int k = 4 * k4 + kk;
    d_Upk[0 * 4096 + idx] = U_i  [k * HID + j];
    d_Upk[1 * 4096 + idx] = U_ste[k * HID + j];
    d_Upk[2 * 4096 + idx] = U_c  [k * HID + j];
    d_Upk[3 * 4096 + idx] = U_o  [k * HID + j];
    if (idx < 16 * FREQ * 4) {
        int fk4 = idx / (FREQ * 4), rr = idx % (FREQ * 4);
        int fj = rr >> 2, fkk = rr & 3;
        d_Ufpk[idx] = U_fre[(4 * fk4 + fkk) * FREQ + fj];
    }
}

// ---------------- trig table, replicating reference fp32 arithmetic ------------------
__global__ void trig_kernel()
{
    int idx = blockIdx.x * blockDim.x + threadIdx.x;   // TSTEPS*FREQ = 1280
    if (idx < TSTEPS * FREQ) {
        int t = idx / FREQ, f = idx % FREQ;
        float fr = (float)f / 10.0f;
        float omega = (6.28318530717958647692f * (float)(t + 1)) * fr;
        d_cosT[idx] = cosf(omega);
        d_sinT[idx] = sinf(omega);
    }
}

// ---------------- phase 1: fused mma.sync GEMM (A converted in-kernel) --------------
#define SA_HI 0
#define SA_LO 5120
#define SB_HI 10240
#define SB_LO 14080
#define STAGE_ELEMS 17920
#define STAGE_BYTES (STAGE_ELEMS * 2)
#define SMEM_GEMM   (2 * STAGE_BYTES)   // 71680 B

__device__ __forceinline__ void load_A(float4* vA, const float* __restrict__ g1,
                                       int kc, int bbase, int t, int tid)
{
    #pragma unroll
    for (int l = 0; l < 8; l++) {
        int idx = tid + l * 128;          // 0..1023 float4 slots
        int row = idx >> 3, g = idx & 7;
        vA[l] = *(const float4*)(g1 +
            ((size_t)(bbase + row) * TSTEPS + t) * INDIM + kc * 32 + g * 4);
    }
}

__device__ __forceinline__ void cvt_sts_A(__nv_bfloat16* sm, int s,
                                          const float4* vA, int tid)
{
    __nv_bfloat16* base = sm + s * STAGE_ELEMS;
    #pragma unroll
    for (int l = 0; l < 8; l++) {
        int idx = tid + l * 128;
        int row = idx >> 3, g = idx & 7;
        float xs[4] = {vA[l].x, vA[l].y, vA[l].z, vA[l].w};
        __nv_bfloat16 h[4], lo[4];
        #pragma unroll
        for (int i = 0; i < 4; i++) {
            h[i]  = __float2bfloat16(xs[i]);
            lo[i] = __float2bfloat16(xs[i] - __bfloat162float(h[i]));
        }
        uint32_t hi01 = (uint32_t)__bfloat16_as_ushort(h[0])  | ((uint32_t)__bfloat16_as_ushort(h[1])  << 16);
        uint32_t hi23 = (uint32_t)__bfloat16_as_ushort(h[2])  | ((uint32_t)__bfloat16_as_ushort(h[3])  << 16);
        uint32_t lo01 = (uint32_t)__bfloat16_as_ushort(lo[0]) | ((uint32_t)__bfloat16_as_ushort(lo[1]) << 16);
        uint32_t lo23 = (uint32_t)__bfloat16_as_ushort(lo[2]) | ((uint32_t)__bfloat16_as_ushort(lo[3]) << 16);
        *(uint2*)(base + SA_HI + row * 40 + g * 4) = make_uint2(hi01, hi23);
        *(uint2*)(base + SA_LO + row * 40 + g * 4) = make_uint2(lo01, lo23);
    }
}

__device__ __forceinline__ void issue_B(__nv_bfloat16* sm, int s, int kc,
                                        int n0, int tid)
{
    __nv_bfloat16* base = sm + s * STAGE_ELEMS;
    #pragma unroll
    for (int l = 0; l < 3; l++) {            // B: 384 chunks (hi+lo pairs)
        int idx = tid + l * 128;
        int row = idx >> 2, g = idx & 3;
        size_t goff = (size_t)(n0 + row) * INDIM + kc * 32 + g * 8;
        cp16(smem_u32(base + SB_HI + row * 40 + g * 8), d_Bhi + goff);
        cp16(smem_u32(base + SB_LO + row * 40 + g * 8), d_Blo + goff);
    }
    CP_COMMIT();
}

__global__ __launch_bounds__(128) void gemm_mma_kernel(const float* __restrict__ g1)
{
    extern __shared__ __align__(16) __nv_bfloat16 sm[];

    const int tid  = threadIdx.x;
    const int lane = tid & 31;
    const int wid  = tid >> 5;
    const int n0   = blockIdx.x * 96;
    const int M0   = blockIdx.y * 128;
    const int t     = M0 >> 10;       // BM=128 divides BSZ -> t constant per block
    const int bbase = M0 & 1023;
    const int wm = (wid & 1) * 64;
    const int wn = (wid >> 1) * 48;

    float d[4][6][4];
    #pragma unroll
    for (int tm = 0; tm < 4; tm++)
        #pragma unroll
        for (int tn = 0; tn < 6; tn++)
            #pragma unroll
            for (int q = 0; q < 4; q++) d[tm][tn][q] = 0.f;

    const int rowA = wm + (lane & 15);
    const int colA = (lane >> 4) * 8;
    const uint32_t relAhi = (uint32_t)(SA_HI + rowA * 40 + colA) * 2;
    const uint32_t relAlo = (uint32_t)(SA_LO + rowA * 40 + colA) * 2;
    const int rowB = wn + ((lane >> 4) * 8) + (lane & 7);
    const int colB = ((lane >> 3) & 1) * 8;
    const uint32_t relBhi = (uint32_t)(SB_HI + rowB * 40 + colB) * 2;
    const uint32_t relBlo = (uint32_t)(SB_LO + rowB * 40 + colB) * 2;
    const uint32_t smbase = smem_u32(sm);

    float4 vA[8];
    load_A(vA, g1, 0, bbase, t, tid);
    cvt_sts_A(sm, 0, vA, tid);
    issue_B(sm, 0, 0, n0, tid);
    load_A(vA, g1, 1, bbase, t, tid);

    for (int kc = 0; kc < 8; kc++) {
        int cur = kc & 1;
        if (kc < 7) {
            cvt_sts_A(sm, cur ^ 1, vA, tid);
            issue_B(sm, cur ^ 1, kc + 1, n0, tid);
            if (kc < 6) load_A(vA, g1, kc + 2, bbase, t, tid);
            CP_WAIT(1);
        } else {
            CP_WAIT(0);
        }
        __syncthreads();

        uint32_t sb = smbase + (uint32_t)cur * STAGE_BYTES;
        #pragma unroll
        for (int ks = 0; ks < 2; ks++) {
            uint32_t ah[4][4], al[4][4], bh[3][4], bl[3][4];
            #pragma unroll
            for (int tm = 0; tm < 4; tm++) {
                uint32_t off = (uint32_t)(tm * 16 * 40 + ks * 16) * 2;
                LDSM4(ah[tm][0], ah[tm][1], ah[tm][2], ah[tm][3], sb + relAhi + off);
                LDSM4(al[tm][0], al[tm][1], al[tm][2], al[tm][3], sb + relAlo + off);
            }
            #pragma unroll
            for (int jB = 0; jB < 3; jB++) {
                uint32_t off = (uint32_t)(jB * 16 * 40 + ks * 16) * 2;
                LDSM4(bh[jB][0], bh[jB][1], bh[jB][2], bh[jB][3], sb + relBhi + off);
                LDSM4(bl[jB][0], bl[jB][1], bl[jB][2], bl[jB][3], sb + relBlo + off);
            }
            #pragma unroll
            for (int tm = 0; tm < 4; tm++)
                #pragma unroll
                for (int tn = 0; tn < 6; tn++) {
                    int jB = tn >> 1, hh = (tn & 1) * 2;
                    MMA16816(d[tm][tn], ah[tm], bh[jB][hh], bh[jB][hh + 1]);
                    MMA16816(d[tm][tn], ah[tm], bl[jB][hh], bl[jB][hh + 1]);
                    MMA16816(d[tm][tn], al[tm], bh[jB][hh], bh[jB][hh + 1]);
                }
        }
        __syncthreads();
    }

    const int mrow = lane >> 2;
    const int ncol = (lane & 3) * 2;
    #pragma unroll
    for (int tn = 0; tn < 6; tn++) {
        int n = n0 + wn + tn * 8 + ncol;
        if (n < NW) {
            float2 bb = *(const float2*)(d_bpack + n);
            #pragma unroll
            for (int tm = 0; tm < 4; tm++) {
                size_t m = (size_t)M0 + wm + tm * 16 + mrow;
                float2 v0 = make_float2(d[tm][tn][0] + bb.x, d[tm][tn][1] + bb.y);
                float2 v1 = make_float2(d[tm][tn][2] + bb.x, d[tm][tn][3] + bb.y);
                *(float2*)(d_pre + m * NW + n)       = v0;
                *(float2*)(d_pre + (m + 8) * NW + n) = v1;
            }
        }
    }
}

// ---------------- phase 2: scan, NB=4, f32x2 GEMV (each dup feeds 2 fma2) -----------
// h stored as u64 pairs in smem; per k per gate: 2 ALU MOVs (dup) + 2 fma2.
// fma-pipe work per step halves vs scalar; alu absorbs dups. Same per-lane rounding.
#define GATE4(acc0, acc1, UPTR)                                          \
    do {                                                                  \
        float4 u = (UPTR)[k4 * 64 + j];                                   \
        u64 dd;                                                           \
        dd = dup2f(u.x); acc0 = fma2(hA.x, dd, acc0); acc1 = fma2(hC.x, dd, acc1); \
        dd = dup2f(u.y); acc0 = fma2(hA.y, dd, acc0); acc1 = fma2(hC.y, dd, acc1); \
        dd = dup2f(u.z); acc0 = fma2(hB.x, dd, acc0); acc1 = fma2(hD.x, dd, acc1); \
        dd = dup2f(u.w); acc0 = fma2(hB.y, dd, acc0); acc1 = fma2(hD.y, dd, acc1); \
    } while (0)

__global__ __launch_bounds__(64, 4) void recurrent_kernel(
    const float* __restrict__ U_a, const float* __restrict__ b_a,
    const float* __restrict__ W_p, const float* __restrict__ b_p,
    const float* __restrict__ fc_w, const float* __restrict__ fc_b,
    float* __restrict__ out)
{
    const int j  = threadIdx.x;
    const int b0 = blockIdx.x * NB;

    __shared__ __align__(16) u64 sh_hP0[HID];   // (h_b0, h_b1)
    __shared__ __align__(16) u64 sh_hP1[HID];   // (h_b2, h_b3)
    __shared__ u64 sh_freP[2][FREQ];
    __shared__ float sh_ct[FREQ], sh_st[FREQ];
    __shared__ float2 sh_red[2][2];             // [warp][pair]

    const float4* U0 = (const float4*)d_Upk;
    const float4* U1 = (const float4*)d_Upk + 1024;
    const float4* U2 = (const float4*)d_Upk + 2048;
    const float4* U3 = (const float4*)d_Upk + 3072;
    const float4* UF = (const float4*)d_Ufpk;
    const ulonglong2* H0 = (const ulonglong2*)sh_hP0;
    const ulonglong2* H1 = (const ulonglong2*)sh_hP1;

    u64 Sre[2][FREQ], Sim[2][FREQ];
    #pragma unroll
    for (int p = 0; p < 2; p++)
        #pragma unroll
        for (int f = 0; f < FREQ; f++) { Sre[p][f] = 0ull; Sim[p][f] = 0ull; }

    float ua[FREQ];
    #pragma unroll
    for (int f = 0; f < FREQ; f++) ua[f] = U_a[f];
    const float ba = b_a[j];

    sh_hP0[j] = 0ull; sh_hP1[j] = 0ull;
    __syncthreads();

    u64 hnP0 = 0ull, hnP1 = 0ull;

    for (int t = 0; t < TSTEPS; t++) {
        const float* r = d_pre + ((size_t)t * BSZ + b0) * NW;
        float pi[NB], ps[NB], pc[NB], po[NB];
        #pragma unroll
        for (int b = 0; b < NB; b++) {
            pi[b] = r[b * NW + j];
            ps[b] = r[b * NW + 64 + j];
            pc[b] = r[b * NW + 138 + j];
            po[b] = r[b * NW + 202 + j];
        }

        u64 ai0 = 0ull, ai1 = 0ull, as0 = 0ull, as1 = 0ull;
        u64 ac0 = 0ull, ac1 = 0ull, ao0 = 0ull, ao1 = 0ull;

        #pragma unroll 4
        for (int k4 = 0; k4 < 16; k4++) {
            ulonglong2 hA = H0[k4 * 2], hB = H0[k4 * 2 + 1];  // pair0: k, k+1 | k+2, k+3
            ulonglong2 hC = H1[k4 * 2], hD = H1[k4 * 2 + 1];  // pair1
            GATE4(ai0, ai1, U0);
            GATE4(as0, as1, U1);
            GATE4(ac0, ac1, U2);
            GATE4(ao0, ao1, U3);
        }

        if (j < FREQ) {
            float pf[NB];
            #pragma unroll
            for (int b = 0; b < NB; b++) pf[b] = r[b * NW + 128 + j];
            u64 af0 = 0ull, af1 = 0ull;
            #pragma unroll 4
            for (int k4 = 0; k4 < 16; k4++) {
                ulonglong2 hA = H0[k4 * 2], hB = H0[k4 * 2 + 1];
                ulonglong2 hC = H1[k4 * 2], hD = H1[k4 * 2 + 1];
                float4 u = UF[k4 * FREQ + j];
                u64 dd;
                dd = dup2f(u.x); af0 = fma2(hA.x, dd, af0); af1 = fma2(hC.x, dd, af1);
                dd = dup2f(u.y); af0 = fma2(hA.y, dd, af0); af1 = fma2(hC.y, dd, af1);
                dd = dup2f(u.z); af0 = fma2(hB.x, dd, af0); af1 = fma2(hD.x, dd, af1);
                dd = dup2f(u.w); af0 = fma2(hB.y, dd, af0); af1 = fma2(hD.y, dd, af1);
            }
            float2 fa = unpack2f(af0);
            float2 fb = unpack2f(af1);
            sh_freP[0][j] = pack2f(hsig(pf[0] + fa.x), hsig(pf[1] + fa.y));
            sh_freP[1][j] = pack2f(hsig(pf[2] + fb.x), hsig(pf[3] + fb.y));
            sh_ct[j] = d_cosT[t * FREQ + j];
            sh_st[j] = d_sinT[t * FREQ + j];
        }

        float2 vi0 = unpack2f(ai0), vi1 = unpack2f(ai1);
        float2 vs0 = unpack2f(as0), vs1 = unpack2f(as1);
        float2 vc0 = unpack2f(ac0), vc1 = unpack2f(ac1);
        float2 vo0 = unpack2f(ao0), vo1 = unpack2f(ao1);
        float gi[NB] = { hsig(pi[0] + vi0.x), hsig(pi[1] + vi0.y),
                         hsig(pi[2] + vi1.x), hsig(pi[3] + vi1.y) };
        float gs[NB] = { hsig(ps[0] + vs0.x), hsig(ps[1] + vs0.y),
                         hsig(ps[2] + vs1.x), hsig(ps[3] + vs1.y) };
        float cc[NB] = { gi[0] * tanhf(pc[0] + vc0.x), gi[1] * tanhf(pc[1] + vc0.y),
                         gi[2] * tanhf(pc[2] + vc1.x), gi[3] * tanhf(pc[3] + vc1.y) };
        float go[NB] = { hsig(po[0] + vo0.x), hsig(po[1] + vo0.y),
                         hsig(po[2] + vo1.x), hsig(po[3] + vo1.y) };

        __syncthreads();   // A: sh_freP/ct/st visible; all sh_h reads done

        u64 ccP[2] = { pack2f(cc[0], cc[1]), pack2f(cc[2], cc[3]) };
        u64 gsP[2] = { pack2f(gs[0], gs[1]), pack2f(gs[2], gs[3]) };
        u64 aaP[2] = { pack2f(ba, ba), pack2f(ba, ba) };
        #pragma unroll
        for (int f = 0; f < FREQ; f++) {
            u64 ctd = dup2f(sh_ct[f]);
            u64 std = dup2f(sh_st[f]);
            u64 uad = dup2f(ua[f]);
            #pragma unroll
            for (int p = 0; p < 2; p++) {
                u64 frP = mul2(gsP[p], sh_freP[p][f]);
                Sre[p][f] = fma2(frP, Sre[p][f], mul2(ccP[p], ctd));
                Sim[p][f] = fma2(frP, Sim[p][f], mul2(ccP[p], std));
                u64 ampP = fma2(Sim[p][f], Sim[p][f], mul2(Sre[p][f], Sre[p][f]));
                aaP[p] = fma2(ampP, uad, aaP[p]);
            }
        }

        float2 a0 = unpack2f(aaP[0]);
        float2 a1 = unpack2f(aaP[1]);
        hnP0 = pack2f(go[0] * tanhf(a0.x), go[1] * tanhf(a0.y));
        hnP1 = pack2f(go[2] * tanhf(a1.x), go[3] * tanhf(a1.y));
        sh_hP0[j] = hnP0;   // safe: all sh_h reads happened before barrier A
        sh_hP1[j] = hnP1;
        __syncthreads();   // B: h(t+1) visible for next iteration
    }

    float vv = 0.f;
    #pragma unroll
    for (int o = 0; o < OUTD; o++) vv = fmaf(W_p[j * OUTD + o], fc_w[o], vv);
    u64 vd = dup2f(vv);
    u64 p0 = mul2(hnP0, vd);
    u64 p1 = mul2(hnP1, vd);
    #pragma unroll
    for (int off = 16; off > 0; off >>= 1) {
        p0 = add2(p0, __shfl_down_sync(0xffffffffu, p0, off));
        p1 = add2(p1, __shfl_down_sync(0xffffffffu, p1, off));
    }
    if ((j & 31) == 0) {
        sh_red[j >> 5][0] = unpack2f(p0);
        sh_red[j >> 5][1] = unpack2f(p1);
    }
    __syncthreads();
    if (j == 0) {
        float s0 = fc_b[0];
        #pragma unroll
        for (int o = 0; o < OUTD; o++) s0 = fmaf(b_p[o], fc_w[o], s0);
        out[b0 + 0] = s0 + sh_red[0][0].x + sh_red[1][0].x;
        out[b0 + 1] = s0 + sh_red[0][0].y + sh_red[1][0].y;
        out[b0 + 2] = s0 + sh_red[0][1].x + sh_red[1][1].x;
        out[b0 + 3] = s0 + sh_red[0][1].y + sh_red[1][1].y;
    }
}

extern "C" void kernel_launch(void* const* d_in, const int* in_sizes, int n_in,
                              void* d_out, int out_size)
{
    const float* g1    = (const float*)d_in[0];
    const float* W_i   = (const float*)d_in[1];
    const float* U_i   = (const float*)d_in[2];
    const float* b_i   = (const float*)d_in[3];
    const float* W_ste = (const float*)d_in[4];
    const float* U_ste = (const float*)d_in[5];
    const float* b_ste = (const float*)d_in[6];
    const float* W_fre = (const float*)d_in[7];
    const float* U_fre = (const float*)d_in[8];
    const float* b_fre = (const float*)d_in[9];
    const float* W_c   = (const float*)d_in[10];
    const float* U_c   = (const float*)d_in[11];
    const float* b_c   = (const float*)d_in[12];
    const float* W_o   = (const float*)d_in[13];
    const float* U_o   = (const float*)d_in[14];
    const float* b_o   = (const float*)d_in[15];
    const float* U_a   = (const float*)d_in[16];
    const float* b_a   = (const float*)d_in[17];
    const float* W_p   = (const float*)d_in[18];
    const float* b_p   = (const float*)d_in[19];
    const float* fc_w  = (const float*)d_in[20];
    const float* fc_b  = (const float*)d_in[21];

    cudaFuncSetAttribute(gemm_mma_kernel,
                         cudaFuncAttributeMaxDynamicSharedMemorySize, SMEM_GEMM);

    pack_w_kernel<<<NPAD, 256>>>(W_i, b_i, W_ste, b_ste, W_fre, b_fre,
                                 W_c, b_c, W_o, b_o);
    pack_u_kernel<<<16, 256>>>(U_i, U_ste, U_c, U_o, U_fre);
    trig_kernel<<<5, 256>>>();
    gemm_mma_kernel<<<dim3(3, 1024), 128, SMEM_GEMM>>>(g1);
    recurrent_kernel<<<BSZ / NB, HID>>>(U_a, b_a, W_p, b_p, fc_w, fc_b,
                                        (float*)d_out);
}

// round 16
// speedup vs baseline: 1.1304x; 1.0086x over previous
#include <cuda_runtime.h>
#include <cuda_bf16.h>
#include <cstdint>

#define BSZ    1024
#define TSTEPS 128
#define INDIM  256
#define HID    64
#define FREQ   10
#define OUTD   16
#define NW     266     // packed gate cols: i(64) | ste(64) | fre(10) | c(64) | o(64)
#define NPAD   288     // padded N: 3 tiles of 96
#define MROWS  (BSZ * TSTEPS)
#define NB     4       // batch elements per recurrent block (2 f32x2 pairs)

typedef unsigned long long u64;

// ----------------- device globals (no runtime allocation) -----------------
__device__ __align__(16) float d_pre[(size_t)MROWS * NW];      // (t*1024+b, 266) fp32
__device__ __align__(16) __nv_bfloat16 d_Bhi[NPAD * INDIM];    // [n][k] bf16 hi
__device__ __align__(16) __nv_bfloat16 d_Blo[NPAD * INDIM];    // [n][k] bf16 lo
__device__ __align__(8)  float d_bpack[NPAD];
__device__ float d_Upk[4 * HID * HID];                          // interleaved [m][k4][j][kk]
__device__ float d_Ufpk[16 * FREQ * 4];
__device__ float d_cosT[TSTEPS * FREQ];
__device__ float d_sinT[TSTEPS * FREQ];

__device__ __forceinline__ float hsig(float x) {
    return fminf(fmaxf(x * (1.0f / 6.0f) + 0.5f, 0.0f), 1.0f);
}

// ---- packed f32x2 helpers ----
__device__ __forceinline__ u64 pack2f(float lo, float hi) {
    u64 r; asm("mov.b64 %0, {%1, %2};" : "=l"(r) : "f"(lo), "f"(hi)); return r;
}
__device__ __forceinline__ float2 unpack2f(u64 v) {
    float2 r; asm("mov.b64 {%0, %1}, %2;" : "=f"(r.x), "=f"(r.y) : "l"(v)); return r;
}
__device__ __forceinline__ u64 dup2f(float x) { return pack2f(x, x); }
__device__ __forceinline__ u64 fma2(u64 a, u64 b, u64 c) {
    u64 d; asm("fma.rn.f32x2 %0, %1, %2, %3;" : "=l"(d) : "l"(a), "l"(b), "l"(c)); return d;
}
__device__ __forceinline__ u64 mul2(u64 a, u64 b) {
    u64 d; asm("mul.rn.f32x2 %0, %1, %2;" : "=l"(d) : "l"(a), "l"(b)); return d;
}
__device__ __forceinline__ u64 add2(u64 a, u64 b) {
    u64 d; asm("add.rn.f32x2 %0, %1, %2;" : "=l"(d) : "l"(a), "l"(b)); return d;
}

__device__ __forceinline__ uint32_t smem_u32(const void* p) {
    uint32_t a;
    asm("{ .reg .u64 t; cvta.to.shared.u64 t, %1; cvt.u32.u64 %0, t; }" : "=r"(a) : "l"(p));
    return a;
}

// ---- base-ISA async copy / mma helpers (no sm_103a-only features) ----
__device__ __forceinline__ void cp16(uint32_t dst, const void* src) {
    asm volatile("cp.async.cg.shared.global [%0], [%1], 16;" :: "r"(dst), "l"(src));
}
#define CP_COMMIT()  asm volatile("cp.async.commit_group;" ::: "memory")
#define CP_WAIT(N)   asm volatile("cp.async.wait_group %0;" :: "n"(N) : "memory")

#define LDSM4(r0, r1, r2, r3, addr) \
    asm volatile("ldmatrix.sync.aligned.m8n8.x4.shared.b16 {%0,%1,%2,%3}, [%4];" \
        : "=r"(r0), "=r"(r1), "=r"(r2), "=r"(r3) : "r"(addr))

#define MMA16816(d, a, b0, b1) \
    asm volatile("mma.sync.aligned.m16n8k16.row.col.f32.bf16.bf16.f32 " \
        "{%0,%1,%2,%3}, {%4,%5,%6,%7}, {%8,%9}, {%0,%1,%2,%3};" \
        : "+f"((d)[0]), "+f"((d)[1]), "+f"((d)[2]), "+f"((d)[3]) \
        : "r"((a)[0]), "r"((a)[1]), "r"((a)[2]), "r"((a)[3]), "r"(b0), "r"(b1))

// ---------------- pack W_* -> Bhi/Blo [288][256] bf16 (+ biases fp32) ---------------
__global__ void pack_w_kernel(const float* __restrict__ W_i,  const float* __restrict__ b_i,
                              const float* __restrict__ W_ste,const float* __restrict__ b_ste,
                              const float* __restrict__ W_fre,const float* __restrict__ b_fre,
                              const float* __restrict__ W_c,  const float* __restrict__ b_c,
                              const float* __restrict__ W_o,  const float* __restrict__ b_o)
{
    int n = blockIdx.x;      // 0..287
    int k = threadIdx.x;     // 0..255
    float w = 0.f, bias = 0.f;
    if (n < 64)       { w = W_i  [k * HID  + n];         bias = b_i  [n]; }
    else if (n < 128) { w = W_ste[k * HID  + (n - 64)];  bias = b_ste[n - 64]; }
    else if (n < 138) { w = W_fre[k * FREQ + (n - 128)]; bias = b_fre[n - 128]; }
    else if (n < 202) { w = W_c  [k * HID  + (n - 138)]; bias = b_c  [n - 138]; }
    else if (n < 266) { w = W_o  [k * HID  + (n - 202)]; bias = b_o  [n - 202]; }
    __nv_bfloat16 h = __float2bfloat16(w);
    __nv_bfloat16 l = __float2bfloat16(w - __bfloat162float(h));
    d_Bhi[n * INDIM + k] = h;
    d_Blo[n * INDIM + k] = l;
    if (k == 0) d_bpack[n] = bias;
}

// -------- interleave U so thread j's float4 = U[4*k4 .. 4*k4+3][j] (warp = 512B) ----
__global__ void pack_u_kernel(const float* __restrict__ U_i, const float* __restrict__ U_ste,
                              const float* __restrict__ U_c, const float* __restrict__ U_o,
                              const float* __restrict__ U_fre)
{
    int idx = blockIdx.x * blockDim.x + threadIdx.x;   // 16 x 256 = 4096
    int k4 = idx >> 8, j = (idx >> 2) & 63, kk = idx & 3;
    int k = 4 * k4 + kk;
    d_Upk[0 * 4096 + idx] = U_i  [k * HID + j];
    d_Upk[1 * 4096 + idx] = U_ste[k * HID + j];
    d_Upk[2 * 4096 + idx] = U_c  [k * HID + j];
    d_Upk[3 * 4096 + idx] = U_o  [k * HID + j];
    if (idx < 16 * FREQ * 4) {
        int fk4 = idx / (FREQ * 4), rr = idx % (FREQ * 4);
        int fj = rr >> 2, fkk = rr & 3;
        d_Ufpk[idx] = U_fre[(4 * fk4 + fkk) * FREQ + fj];
    }
}

// ---------------- trig table, replicating reference fp32 arithmetic ------------------
__global__ void trig_kernel()
{
    int idx = blockIdx.x * blockDim.x + threadIdx.x;   // TSTEPS*FREQ = 1280
    if (idx < TSTEPS * FREQ) {
        int t = idx / FREQ, f = idx % FREQ;
        float fr = (float)f / 10.0f;
        float omega = (6.28318530717958647692f * (float)(t + 1)) * fr;
        d_cosT[idx] = cosf(omega);
        d_sinT[idx] = sinf(omega);
    }
}

// ---------------- phase 1: fused mma.sync GEMM, 256 thr / 8 warps -------------------
// Block tile M=128 x N=96; warp grid 4(m) x 2(n); warp tile 32x48 (2x6 m16n8k16).
// Halved per-thread accumulators (48) -> ~120 regs -> 2 blocks/SM -> 16 warps/SM.
#define SA_HI 0
#define SA_LO 5120
#define SB_HI 10240
#define SB_LO 14080
#define STAGE_ELEMS 17920
#define STAGE_BYTES (STAGE_ELEMS * 2)
#define SMEM_GEMM   (2 * STAGE_BYTES)   // 71680 B

__device__ __forceinline__ void load_A(float4* vA, const float* __restrict__ g1,
                                       int kc, int bbase, int t, int tid)
{
    #pragma unroll
    for (int l = 0; l < 4; l++) {
        int idx = tid + l * 256;          // 0..1023 float4 slots
        int row = idx >> 3, g = idx & 7;
        vA[l] = *(const float4*)(g1 +
            ((size_t)(bbase + row) * TSTEPS + t) * INDIM + kc * 32 + g * 4);
    }
}

__device__ __forceinline__ void cvt_sts_A(__nv_bfloat16* sm, int s,
                                          const float4* vA, int tid)
{
    __nv_bfloat16* base = sm + s * STAGE_ELEMS;
    #pragma unroll
    for (int l = 0; l < 4; l++) {
        int idx = tid + l * 256;
        int row = idx >> 3, g = idx & 7;
        float xs[4] = {vA[l].x, vA[l].y, vA[l].z, vA[l].w};
        __nv_bfloat16 h[4], lo[4];
        #pragma unroll
        for (int i = 0; i < 4; i++) {
            h[i]  = __float2bfloat16(xs[i]);
            lo[i] = __float2bfloat16(xs[i] - __bfloat162float(h[i]));
        }
        uint32_t hi01 = (uint32_t)__bfloat16_as_ushort(h[0])  | ((uint32_t)__bfloat16_as_ushort(h[1])  << 16);
        uint32_t hi23 = (uint32_t)__bfloat16_as_ushort(h[2])  | ((uint32_t)__bfloat16_as_ushort(h[3])  << 16);
        uint32_t lo01 = (uint32_t)__bfloat16_as_ushort(lo[0]) | ((uint32_t)__bfloat16_as_ushort(lo[1]) << 16);
        uint32_t lo23 = (uint32_t)__bfloat16_as_ushort(lo[2]) | ((uint32_t)__bfloat16_as_ushort(lo[3]) << 16);
        *(uint2*)(base + SA_HI + row * 40 + g * 4) = make_uint2(hi01, hi23);
        *(uint2*)(base + SA_LO + row * 40 + g * 4) = make_uint2(lo01, lo23);
    }
}

__device__ __forceinline__ void issue_B(__nv_bfloat16* sm, int s, int kc,
                                        int n0, int tid)
{
    __nv_bfloat16* base = sm + s * STAGE_ELEMS;
    #pragma unroll
    for (int l = 0; l < 2; l++) {            // B: 384 chunk-pairs over 256 threads
        int idx = tid + l * 256;
        if (idx < 384) {
            int row = idx >> 2, g = idx & 3;
            size_t goff = (size_t)(n0 + row) * INDIM + kc * 32 + g * 8;
            cp16(smem_u32(base + SB_HI + row * 40 + g * 8), d_Bhi + goff);
            cp16(smem_u32(base + SB_LO + row * 40 + g * 8), d_Blo + goff);
        }
    }
    CP_COMMIT();
}

__global__ __launch_bounds__(256, 2) void gemm_mma_kernel(const float* __restrict__ g1)
{
    extern __shared__ __align__(16) __nv_bfloat16 sm[];

    const int tid  = threadIdx.x;
    const int lane = tid & 31;
    const int wid  = tid >> 5;          // 0..7
    const int n0   = blockIdx.x * 96;
    const int M0   = blockIdx.y * 128;
    const int t     = M0 >> 10;         // BM=128 divides BSZ -> t constant per block
    const int bbase = M0 & 1023;
    const int wm = (wid & 3) * 32;      // 4 warps across M
    const int wn = (wid >> 2) * 48;     // 2 warps across N

    float d[2][6][4];
    #pragma unroll
    for (int tm = 0; tm < 2; tm++)
        #pragma unroll
        for (int tn = 0; tn < 6; tn++)
            #pragma unroll
            for (int q = 0; q < 4; q++) d[tm][tn][q] = 0.f;

    const int rowA = wm + (lane & 15);
    const int colA = (lane >> 4) * 8;
    const uint32_t relAhi = (uint32_t)(SA_HI + rowA * 40 + colA) * 2;
    const uint32_t relAlo = (uint32_t)(SA_LO + rowA * 40 + colA) * 2;
    const int rowB = wn + ((lane >> 4) * 8) + (lane & 7);
    const int colB = ((lane >> 3) & 1) * 8;
    const uint32_t relBhi = (uint32_t)(SB_HI + rowB * 40 + colB) * 2;
    const uint32_t relBlo = (uint32_t)(SB_LO + rowB * 40 + colB) * 2;
    const uint32_t smbase = smem_u32(sm);

    float4 vA[4];
    load_A(vA, g1, 0, bbase, t, tid);
    cvt_sts_A(sm, 0, vA, tid);
    issue_B(sm, 0, 0, n0, tid);
    load_A(vA, g1, 1, bbase, t, tid);

    for (int kc = 0; kc < 8; kc++) {
        int cur = kc & 1;
        if (kc < 7) {
            cvt_sts_A(sm, cur ^ 1, vA, tid);
            issue_B(sm, cur ^ 1, kc + 1, n0, tid);
            if (kc < 6) load_A(vA, g1, kc + 2, bbase, t, tid);
            CP_WAIT(1);
        } else {
            CP_WAIT(0);
        }
        __syncthreads();

        uint32_t sb = smbase + (uint32_t)cur * STAGE_BYTES;
        #pragma unroll
        for (int ks = 0; ks < 2; ks++) {
            uint32_t ah[2][4], al[2][4], bh[3][4], bl[3][4];
            #pragma unroll
            for (int tm = 0; tm < 2; tm++) {
                uint32_t off = (uint32_t)(tm * 16 * 40 + ks * 16) * 2;
                LDSM4(ah[tm][0], ah[tm][1], ah[tm][2], ah[tm][3], sb + relAhi + off);
                LDSM4(al[tm][0], al[tm][1], al[tm][2], al[tm][3], sb + relAlo + off);
            }
            #pragma unroll
            for (int jB = 0; jB < 3; jB++) {
                uint32_t off = (uint32_t)(jB * 16 * 40 + ks * 16) * 2;
                LDSM4(bh[jB][0], bh[jB][1], bh[jB][2], bh[jB][3], sb + relBhi + off);
                LDSM4(bl[jB][0], bl[jB][1], bl[jB][2], bl[jB][3], sb + relBlo + off);
            }
            #pragma unroll
            for (int tm = 0; tm < 2; tm++)
                #pragma unroll
                for (int tn = 0; tn < 6; tn++) {
                    int jB = tn >> 1, hh = (tn & 1) * 2;
                    MMA16816(d[tm][tn], ah[tm], bh[jB][hh], bh[jB][hh + 1]);
                    MMA16816(d[tm][tn], ah[tm], bl[jB][hh], bl[jB][hh + 1]);
                    MMA16816(d[tm][tn], al[tm], bh[jB][hh], bh[jB][hh + 1]);
                }
        }
        __syncthreads();
    }

    const int mrow = lane >> 2;
    const int ncol = (lane & 3) * 2;
    #pragma unroll
    for (int tn = 0; tn < 6; tn++) {
        int n = n0 + wn + tn * 8 + ncol;
        if (n < NW) {
            float2 bb = *(const float2*)(d_bpack + n);
            #pragma unroll
            for (int tm = 0; tm < 2; tm++) {
                size_t m = (size_t)M0 + wm + tm * 16 + mrow;
                float2 v0 = make_float2(d[tm][tn][0] + bb.x, d[tm][tn][1] + bb.y);
                float2 v1 = make_float2(d[tm][tn][2] + bb.x, d[tm][tn][3] + bb.y);
                *(float2*)(d_pre + m * NW + n)       = v0;
                *(float2*)(d_pre + (m + 8) * NW + n) = v1;
            }
        }
    }
}

// ---------------- phase 2: scan, NB=4, f32x2 GEMV (R15 measured-best) ---------------
#define GATE4(acc0, acc1, UPTR)                                          \
    do {                                                                  \
        float4 u = (UPTR)[k4 * 64 + j];                                   \
        u64 dd;                                                           \
        dd = dup2f(u.x); acc0 = fma2(hA.x, dd, acc0); acc1 = fma2(hC.x, dd, acc1); \
        dd = dup2f(u.y); acc0 = fma2(hA.y, dd, acc0); acc1 = fma2(hC.y, dd, acc1); \
        dd = dup2f(u.z); acc0 = fma2(hB.x, dd, acc0); acc1 = fma2(hD.x, dd, acc1); \
        dd = dup2f(u.w); acc0 = fma2(hB.y, dd, acc0); acc1 = fma2(hD.y, dd, acc1); \
    } while (0)

__global__ __launch_bounds__(64, 4) void recurrent_kernel(
    const float* __restrict__ U_a, const float* __restrict__ b_a,
    const float* __restrict__ W_p, const float* __restrict__ b_p,
    const float* __restrict__ fc_w, const float* __restrict__ fc_b,
    float* __restrict__ out)
{
    const int j  = threadIdx.x;
    const int b0 = blockIdx.x * NB;

    __shared__ __align__(16) u64 sh_hP0[HID];   // (h_b0, h_b1)
    __shared__ __align__(16) u64 sh_hP1[HID];   // (h_b2, h_b3)
    __shared__ u64 sh_freP[2][FREQ];
    __shared__ float sh_ct[FREQ], sh_st[FREQ];
    __shared__ float2 sh_red[2][2];             // [warp][pair]

    const float4* U0 = (const float4*)d_Upk;
    const float4* U1 = (const float4*)d_Upk + 1024;
    const float4* U2 = (const float4*)d_Upk + 2048;
    const float4* U3 = (const float4*)d_Upk + 3072;
    const float4* UF = (const float4*)d_Ufpk;
    const ulonglong2* H0 = (const ulonglong2*)sh_hP0;
    const ulonglong2* H1 = (const ulonglong2*)sh_hP1;

    u64 Sre[2][FREQ], Sim[2][FREQ];
    #pragma unroll
    for (int p = 0; p < 2; p++)
        #pragma unroll
        for (int f = 0; f < FREQ; f++) { Sre[p][f] = 0ull; Sim[p][f] = 0ull; }

    float ua[FREQ];
    #pragma unroll
    for (int f = 0; f < FREQ; f++) ua[f] = U_a[f];
    const float ba = b_a[j];

    sh_hP0[j] = 0ull; sh_hP1[j] = 0ull;
    __syncthreads();

    u64 hnP0 = 0ull, hnP1 = 0ull;

    for (int t = 0; t < TSTEPS; t++) {
        const float* r = d_pre + ((size_t)t * BSZ + b0) * NW;
        float pi[NB], ps[NB], pc[NB], po[NB];
        #pragma unroll
        for (int b = 0; b < NB; b++) {
            pi[b] = r[b * NW + j];
            ps[b] = r[b * NW + 64 + j];
            pc[b] = r[b * NW + 138 + j];
            po[b] = r[b * NW + 202 + j];
        }

        u64 ai0 = 0ull, ai1 = 0ull, as0 = 0ull, as1 = 0ull;
        u64 ac0 = 0ull, ac1 = 0ull, ao0 = 0ull, ao1 = 0ull;

        #pragma unroll 4
        for (int k4 = 0; k4 < 16; k4++) {
            ulonglong2 hA = H0[k4 * 2], hB = H0[k4 * 2 + 1];
            ulonglong2 hC = H1[k4 * 2], hD = H1[k4 * 2 + 1];
            GATE4(ai0, ai1, U0);
            GATE4(as0, as1, U1);
            GATE4(ac0, ac1, U2);
            GATE4(ao0, ao1, U3);
        }

        if (j < FREQ) {
            float pf[NB];
            #pragma unroll
            for (int b = 0; b < NB; b++) pf[b] = r[b * NW + 128 + j];
            u64 af0 = 0ull, af1 = 0ull;
            #pragma unroll 4
            for (int k4 = 0; k4 < 16; k4++) {
                ulonglong2 hA = H0[k4 * 2], hB = H0[k4 * 2 + 1];
                ulonglong2 hC = H1[k4 * 2], hD = H1[k4 * 2 + 1];
                float4 u = UF[k4 * FREQ + j];
                u64 dd;
                dd = dup2f(u.x); af0 = fma2(hA.x, dd, af0); af1 = fma2(hC.x, dd, af1);
                dd = dup2f(u.y); af0 = fma2(hA.y, dd, af0); af1 = fma2(hC.y, dd, af1);
                dd = dup2f(u.z); af0 = fma2(hB.x, dd, af0); af1 = fma2(hD.x, dd, af1);
                dd = dup2f(u.w); af0 = fma2(hB.y, dd, af0); af1 = fma2(hD.y, dd, af1);
            }
            float2 fa = unpack2f(af0);
            float2 fb = unpack2f(af1);
            sh_freP[0][j] = pack2f(hsig(pf[0] + fa.x), hsig(pf[1] + fa.y));
            sh_freP[1][j] = pack2f(hsig(pf[2] + fb.x), hsig(pf[3] + fb.y));
            sh_ct[j] = d_cosT[t * FREQ + j];
            sh_st[j] = d_sinT[t * FREQ + j];
        }

        float2 vi0 = unpack2f(ai0), vi1 = unpack2f(ai1);
        float2 vs0 = unpack2f(as0), vs1 = unpack2f(as1);
        float2 vc0 = unpack2f(ac0), vc1 = unpack2f(ac1);
        float2 vo0 = unpack2f(ao0), vo1 = unpack2f(ao1);
        float gi[NB] = { hsig(pi[0] + vi0.x), hsig(pi[1] + vi0.y),
                         hsig(pi[2] + vi1.x), hsig(pi[3] + vi1.y) };
        float gs[NB] = { hsig(ps[0] + vs0.x), hsig(ps[1] + vs0.y),
                         hsig(ps[2] + vs1.x), hsig(ps[3] + vs1.y) };
        float cc[NB] = { gi[0] * tanhf(pc[0] + vc0.x), gi[1] * tanhf(pc[1] + vc0.y),
                         gi[2] * tanhf(pc[2] + vc1.x), gi[3] * tanhf(pc[3] + vc1.y) };
        float go[NB] = { hsig(po[0] + vo0.x), hsig(po[1] + vo0.y),
                         hsig(po[2] + vo1.x), hsig(po[3] + vo1.y) };

        __syncthreads();   // A: sh_freP/ct/st visible; all sh_h reads done

        u64 ccP[2] = { pack2f(cc[0], cc[1]), pack2f(cc[2], cc[3]) };
        u64 gsP[2] = { pack2f(gs[0], gs[1]), pack2f(gs[2], gs[3]) };
        u64 aaP[2] = { pack2f(ba, ba), pack2f(ba, ba) };
        #pragma unroll
        for (int f = 0; f < FREQ; f++) {
            u64 ctd = dup2f(sh_ct[f]);
            u64 std = dup2f(sh_st[f]);
            u64 uad = dup2f(ua[f]);
            #pragma unroll
            for (int p = 0; p < 2; p++) {
                u64 frP = mul2(gsP[p], sh_freP[p][f]);
                Sre[p][f] = fma2(frP, Sre[p][f], mul2(ccP[p], ctd));
                Sim[p][f] = fma2(frP, Sim[p][f], mul2(ccP[p], std));
                u64 ampP = fma2(Sim[p][f], Sim[p][f], mul2(Sre[p][f], Sre[p][f]));
                aaP[p] = fma2(ampP, uad, aaP[p]);
            }
        }

        float2 a0 = unpack2f(aaP[0]);
        float2 a1 = unpack2f(aaP[1]);
        hnP0 = pack2f(go[0] * tanhf(a0.x), go[1] * tanhf(a0.y));
        hnP1 = pack2f(go[2] * tanhf(a1.x), go[3] * tanhf(a1.y));
        sh_hP0[j] = hnP0;   // safe: all sh_h reads happened before barrier A
        sh_hP1[j] = hnP1;
        __syncthreads();   // B: h(t+1) visible for next iteration
    }

    float vv = 0.f;
    #pragma unroll
    for (int o = 0; o < OUTD; o++) vv = fmaf(W_p[j * OUTD + o], fc_w[o], vv);
    u64 vd = dup2f(vv);
    u64 p0 = mul2(hnP0, vd);
    u64 p1 = mul2(hnP1, vd);
    #pragma unroll
    for (int off = 16; off > 0; off >>= 1) {
        p0 = add2(p0, __shfl_down_sync(0xffffffffu, p0, off));
        p1 = add2(p1, __shfl_down_sync(0xffffffffu, p1, off));
    }
    if ((j & 31) == 0) {
        sh_red[j >> 5][0] = unpack2f(p0);
        sh_red[j >> 5][1] = unpack2f(p1);
    }
    __syncthreads();
    if (j == 0) {
        float s0 = fc_b[0];
        #pragma unroll
        for (int o = 0; o < OUTD; o++) s0 = fmaf(b_p[o], fc_w[o], s0);
        out[b0 + 0] = s0 + sh_red[0][0].x + sh_red[1][0].x;
        out[b0 + 1] = s0 + sh_red[0][0].y + sh_red[1][0].y;
        out[b0 + 2] = s0 + sh_red[0][1].x + sh_red[1][1].x;
        out[b0 + 3] = s0 + sh_red[0][1].y + sh_red[1][1].y;
    }
}

extern "C" void kernel_launch(void* const* d_in, const int* in_sizes, int n_in,
                              void* d_out, int out_size)
{
    const float* g1    = (const float*)d_in[0];
    const float* W_i   = (const float*)d_in[1];
    const float* U_i   = (const float*)d_in[2];
    const float* b_i   = (const float*)d_in[3];
    const float* W_ste = (const float*)d_in[4];
    const float* U_ste = (const float*)d_in[5];
    const float* b_ste = (const float*)d_in[6];
    const float* W_fre = (const float*)d_in[7];
    const float* U_fre = (const float*)d_in[8];
    const float* b_fre = (const float*)d_in[9];
    const float* W_c   = (const float*)d_in[10];
    const float* U_c   = (const float*)d_in[11];
    const float* b_c   = (const float*)d_in[12];
    const float* W_o   = (const float*)d_in[13];
    const float* U_o   = (const float*)d_in[14];
    const float* b_o   = (const float*)d_in[15];
    const float* U_a   = (const float*)d_in[16];
    const float* b_a   = (const float*)d_in[17];
    const float* W_p   = (const float*)d_in[18];
    const float* b_p   = (const float*)d_in[19];
    const float* fc_w  = (const float*)d_in[20];
    const float* fc_b  = (const float*)d_in[21];

    cudaFuncSetAttribute(gemm_mma_kernel,
                         cudaFuncAttributeMaxDynamicSharedMemorySize, SMEM_GEMM);

    pack_w_kernel<<<NPAD, 256>>>(W_i, b_i, W_ste, b_ste, W_fre, b_fre,
                                 W_c, b_c, W_o, b_o);
    pack_u_kernel<<<16, 256>>>(U_i, U_ste, U_c, U_o, U_fre);
    trig_kernel<<<5, 256>>>();
    gemm_mma_kernel<<<dim3(3, 1024), 256, SMEM_GEMM>>>(g1);
    recurrent_kernel<<<BSZ / NB, HID>>>(U_a, b_a, W_p, b_p, fc_w, fc_b,
                                        (float*)d_out);
}